// round 12
// baseline (speedup 1.0000x reference)
#include <cuda_runtime.h>
#include <cuda_fp16.h>
#include <cstdint>

#define BATCH   8
#define SEQ     1024
#define DMODEL  1024
#define NHEAD   16
#define HDIM    64
#define DFF     4096
#define NROWS   (BATCH * SEQ)           // 8192
#define QKVN    (3 * DMODEL)            // 3072

// ---------------------------------------------------------------------------
// Scratch buffers
// ---------------------------------------------------------------------------
__device__ __half g_Xh   [NROWS * DMODEL];
__device__ __half g_QKVh [NROWS * QKVN];
__device__ __half g_CTXh [NROWS * DMODEL];
__device__ __half g_X1h  [NROWS * DMODEL];
__device__ __half g_Hh   [NROWS * DFF];
__device__ float  g_AO   [NROWS * DMODEL];
__device__ float  g_X1   [NROWS * DMODEL];
__device__ float  g_F    [NROWS * DMODEL];
// transposed fp16 weights [N][K]
__device__ __half g_WqkvTh[QKVN * DMODEL];
__device__ __half g_WoTh  [DMODEL * DMODEL];
__device__ __half g_W1Th  [DFF * DMODEL];
__device__ __half g_W2Th  [DMODEL * DFF];

// ---------------------------------------------------------------------------
// Helpers
// ---------------------------------------------------------------------------
__device__ __forceinline__ unsigned smem_u32(const void* p) {
    return (unsigned)__cvta_generic_to_shared(p);
}
__device__ __forceinline__ void cp16(unsigned s, const void* g) {
    asm volatile("cp.async.cg.shared.global [%0], [%1], 16;" :: "r"(s), "l"(g));
}
__device__ __forceinline__ void cp_commit() {
    asm volatile("cp.async.commit_group;");
}
template <int N>
__device__ __forceinline__ void cp_wait() {
    asm volatile("cp.async.wait_group %0;" :: "n"(N));
}
__device__ __forceinline__ void mma16(
    float& c0, float& c1, float& c2, float& c3,
    unsigned a0, unsigned a1, unsigned a2, unsigned a3,
    unsigned b0, unsigned b1)
{
    asm volatile(
        "mma.sync.aligned.m16n8k16.row.col.f32.f16.f16.f32 "
        "{%0,%1,%2,%3},{%4,%5,%6,%7},{%8,%9},{%0,%1,%2,%3};"
        : "+f"(c0), "+f"(c1), "+f"(c2), "+f"(c3)
        : "r"(a0), "r"(a1), "r"(a2), "r"(a3), "r"(b0), "r"(b1));
}
__device__ __forceinline__ void ldsm4(
    unsigned& r0, unsigned& r1, unsigned& r2, unsigned& r3, unsigned addr)
{
    asm volatile("ldmatrix.sync.aligned.m8n8.x4.shared.b16 {%0,%1,%2,%3}, [%4];"
        : "=r"(r0), "=r"(r1), "=r"(r2), "=r"(r3) : "r"(addr));
}
__device__ __forceinline__ void ldsm4t(
    unsigned& r0, unsigned& r1, unsigned& r2, unsigned& r3, unsigned addr)
{
    asm volatile("ldmatrix.sync.aligned.m8n8.x4.trans.shared.b16 {%0,%1,%2,%3}, [%4];"
        : "=r"(r0), "=r"(r1), "=r"(r2), "=r"(r3) : "r"(addr));
}
// packed 2^x for two fp16 values
__device__ __forceinline__ unsigned ex2h2(unsigned x) {
    unsigned r;
    asm("ex2.approx.f16x2 %0, %1;" : "=r"(r) : "r"(x));
    return r;
}
__device__ __forceinline__ unsigned packh2f(float a, float b) {
    __half2 h = __floats2half2_rn(a, b);
    return *(unsigned*)&h;
}

// ---------------------------------------------------------------------------
// Mask accessor
// ---------------------------------------------------------------------------
__device__ __forceinline__ int mask_mode(const void* mask) {
    unsigned w0 = *(const unsigned*)mask;
    return (w0 == 0x01010101u) ? 0 : 1;
}
__device__ __forceinline__ bool mask_ok(const void* mask, int mode, size_t idx) {
    if (mode == 0) return ((const unsigned char*)mask)[idx] != 0;
    return ((const unsigned*)mask)[idx] != 0u;
}

// ---------------------------------------------------------------------------
// Prep kernels
// ---------------------------------------------------------------------------
__global__ void __launch_bounds__(256) f2h_k(
    const float* __restrict__ in, __half* __restrict__ out, int n)
{
    int i = (blockIdx.x * 256 + threadIdx.x) * 4;
    if (i < n) {
        float4 v = *(const float4*)(in + i);
        *(__half2*)(out + i)     = __floats2half2_rn(v.x, v.y);
        *(__half2*)(out + i + 2) = __floats2half2_rn(v.z, v.w);
    }
}

// up to 3 fused transposes per launch; 64(k) x 32(n) tile, half2 stores.
// out[n*K + k] = half(in[k*N + n])
struct TPJobs {
    const float* in[3];
    __half* out[3];
    int K[3], N[3], cum[3], cnt;
};
__global__ void __launch_bounds__(256) transp_k(TPJobs J)
{
    __shared__ float tile[64][33];
    int bid = blockIdx.x;
    int z = 0;
    while (z < J.cnt - 1 && bid >= J.cum[z]) z++;
    int lt = bid - (z ? J.cum[z - 1] : 0);
    const int K = J.K[z], N = J.N[z];
    const int ntk = K >> 6;                  // tiles along k
    const int kb = (lt % ntk) * 64;
    const int nb = (lt / ntk) * 32;
    const float* in = J.in[z];
    __half* out = J.out[z];
    const int tx = threadIdx.x & 31, wy = threadIdx.x >> 5;   // 32 x 8

    // load 64 rows x 32 cols, coalesced (128B per warp row)
#pragma unroll
    for (int i = wy; i < 64; i += 8)
        tile[i][tx] = in[(size_t)(kb + i) * N + nb + tx];
    __syncthreads();

    // store: each warp handles n-rows wy, wy+8, wy+16, wy+24; lane writes half2
#pragma unroll
    for (int p = 0; p < 4; p++) {
        const int n = wy + p * 8;
        __half2 v = __floats2half2_rn(tile[tx * 2][n], tile[tx * 2 + 1][n]);
        *(__half2*)(out + (size_t)(nb + n) * K + kb + tx * 2) = v;
    }
}

// ---------------------------------------------------------------------------
// fp16 GEMM, cp.async 2-stage, LDSM fragments: C = A @ Bt^T (+bias)(+relu)
// ---------------------------------------------------------------------------
#define TS 40
#define HSTAGE (128 * TS)
#define GEMM_SMEM (4 * HSTAGE * 2)    // 40960 B

template <int EPI, int OUTF>
__global__ void __launch_bounds__(128, 2) hgemm_k(
    const __half* __restrict__ A, const __half* __restrict__ Bt,
    const float* __restrict__ bias, void* __restrict__ Cv,
    int M, int N, int K)
{
    extern __shared__ __half hsm[];
    __half* Asm[2] = { hsm,              hsm + HSTAGE     };
    __half* Bsm[2] = { hsm + 2 * HSTAGE, hsm + 3 * HSTAGE };

    const int t    = threadIdx.x;
    const int lane = t & 31, warp = t >> 5;
    const int gid  = lane >> 2, tig = lane & 3;
    const int r8   = lane & 7,  g8  = lane >> 3;
    const int wm   = (warp & 1) * 64;
    const int wn   = (warp >> 1) * 64;
    const int bx   = blockIdx.x, by = blockIdx.y;

    const int lr = t >> 2, lch = (t & 3) * 8;

    const __half* Abase = A  + (size_t)(by * 128 + lr) * K + lch;
    const __half* Bbase = Bt + (size_t)(bx * 128 + lr) * K + lch;

    auto issue = [&](int kt, int s) {
        const __half* Ag = Abase + kt * 32;
        const __half* Bg = Bbase + kt * 32;
        __half* ad = Asm[s];
        __half* bd = Bsm[s];
#pragma unroll
        for (int p = 0; p < 4; p++) {
            cp16(smem_u32(&ad[(lr + p * 32) * TS + lch]), Ag + (size_t)(p * 32) * K);
            cp16(smem_u32(&bd[(lr + p * 32) * TS + lch]), Bg + (size_t)(p * 32) * K);
        }
        cp_commit();
    };

    const int aOff = (wm + r8 + (g8 & 1) * 8) * TS + (g8 >> 1) * 8;
    const int bOff = (wn + r8 + (g8 >> 1) * 8) * TS + (g8 & 1) * 8;
    const unsigned asB[2] = { smem_u32(Asm[0]), smem_u32(Asm[1]) };
    const unsigned bsB[2] = { smem_u32(Bsm[0]), smem_u32(Bsm[1]) };

    float acc[4][8][4];
#pragma unroll
    for (int i = 0; i < 4; i++)
#pragma unroll
        for (int j = 0; j < 8; j++)
#pragma unroll
            for (int r = 0; r < 4; r++) acc[i][j][r] = 0.f;

    const int nkt = K >> 5;
    issue(0, 0);
    issue(1, 1);
    cp_wait<1>();
    __syncthreads();

    for (int kt = 0; kt < nkt; ++kt) {
        const int s = kt & 1;
#pragma unroll
        for (int ks = 0; ks < 2; ++ks) {
            const int kc = ks * 16;
            unsigned af[4][4], bf[8][2];
#pragma unroll
            for (int i = 0; i < 4; i++)
                ldsm4(af[i][0], af[i][1], af[i][2], af[i][3],
                      asB[s] + (unsigned)(aOff + i * 16 * TS + kc) * 2u);
#pragma unroll
            for (int jp = 0; jp < 4; jp++)
                ldsm4(bf[2*jp][0], bf[2*jp][1], bf[2*jp+1][0], bf[2*jp+1][1],
                      bsB[s] + (unsigned)(bOff + jp * 16 * TS + kc) * 2u);
#pragma unroll
            for (int i = 0; i < 4; i++)
#pragma unroll
                for (int j = 0; j < 8; j++)
                    mma16(acc[i][j][0], acc[i][j][1], acc[i][j][2], acc[i][j][3],
                          af[i][0], af[i][1], af[i][2], af[i][3],
                          bf[j][0], bf[j][1]);
        }
        __syncthreads();
        if (kt + 2 < nkt) {
            issue(kt + 2, s);
            cp_wait<1>();
        } else {
            cp_wait<0>();
        }
        __syncthreads();
    }

#pragma unroll
    for (int i = 0; i < 4; i++) {
        const int r0 = by * 128 + wm + i * 16 + gid;
#pragma unroll
        for (int j = 0; j < 8; j++) {
            const int c0 = bx * 128 + wn + j * 8 + 2 * tig;
            float v0 = acc[i][j][0], v1 = acc[i][j][1];
            float v2 = acc[i][j][2], v3 = acc[i][j][3];
            if (EPI >= 1) {
                float b0 = bias[c0], b1 = bias[c0 + 1];
                v0 += b0; v1 += b1; v2 += b0; v3 += b1;
            }
            if (EPI == 2) {
                v0 = fmaxf(v0, 0.f); v1 = fmaxf(v1, 0.f);
                v2 = fmaxf(v2, 0.f); v3 = fmaxf(v3, 0.f);
            }
            if (OUTF == 1) {
                __half* C = (__half*)Cv;
                *(__half2*)(C + (size_t)r0 * N + c0)       = __floats2half2_rn(v0, v1);
                *(__half2*)(C + (size_t)(r0 + 8) * N + c0) = __floats2half2_rn(v2, v3);
            } else {
                float* C = (float*)Cv;
                *(float2*)(C + (size_t)r0 * N + c0)       = make_float2(v0, v1);
                *(float2*)(C + (size_t)(r0 + 8) * N + c0) = make_float2(v2, v3);
            }
        }
    }
}

// ---------------------------------------------------------------------------
// Flash attention: fp16, 2-stage K/V, register P, f16x2 exp softmax.
// Q/K/V in fused QKV buffer [NROWS][3072]: Q@0, K@1024, V@2048.
// ---------------------------------------------------------------------------
#define KVS 72
#define KV_TILEH (64 * KVS)
#define ATTN_SMEM ((4 * KV_TILEH + 128 * KVS) * 2)       // 55296 B

__global__ void __launch_bounds__(256, 1) attn_k(
    const __half* __restrict__ QKV, const void* __restrict__ mask,
    __half* __restrict__ CTX)
{
    extern __shared__ __half smh[];
    __half* ksm[2] = { smh,                smh + KV_TILEH     };
    __half* vsm[2] = { smh + 2 * KV_TILEH, smh + 3 * KV_TILEH };
    __half* ps     = smh + 4 * KV_TILEH;

    const int qb = blockIdx.x, h = blockIdx.y, b = blockIdx.z;
    const int t = threadIdx.x, lane = t & 31, warp = t >> 5;
    const int gid = lane >> 2, tig = lane & 3;
    const int r8 = lane & 7, g8 = lane >> 3;
    const int q0 = qb * 128;
    const size_t baseq = (size_t)b * SEQ * QKVN + (size_t)h * HDIM;
    const size_t baseo = (size_t)b * SEQ * DMODEL + (size_t)h * HDIM;

    const int lr = t >> 3;
    const int lch = (t & 7) * 8;

    auto issue = [&](int kt, int s) {
        const __half* Kg = QKV + baseq + DMODEL     + (size_t)(kt * 64) * QKVN;
        const __half* Vg = QKV + baseq + 2 * DMODEL + (size_t)(kt * 64) * QKVN;
        __half* kd = ksm[s];
        __half* vd = vsm[s];
#pragma unroll
        for (int p = 0; p < 2; p++) {
            int r = p * 32 + lr;
            cp16(smem_u32(&kd[r * KVS + lch]), Kg + (size_t)r * QKVN + lch);
            cp16(smem_u32(&vd[r * KVS + lch]), Vg + (size_t)r * QKVN + lch);
        }
        cp_commit();
    };

    issue(0, 0);
    issue(1, 1);

    __half* pw = ps + warp * 16 * KVS;
    {
        const int row = lane >> 1;
        const int colh = (lane & 1) * 32;
        const uint4* qg4 = (const uint4*)(QKV + baseq + (size_t)(q0 + warp * 16 + row) * QKVN + colh);
        uint4* qp4 = (uint4*)(pw + row * KVS + colh);
#pragma unroll
        for (int i = 0; i < 4; i++) qp4[i] = qg4[i];
    }
    __syncwarp();

    const unsigned pwB = smem_u32(pw);
    const unsigned ksB[2] = { smem_u32(ksm[0]), smem_u32(ksm[1]) };
    const unsigned vsB[2] = { smem_u32(vsm[0]), smem_u32(vsm[1]) };
    const int paOff = (r8 + (g8 & 1) * 8) * KVS + (g8 >> 1) * 8;
    const int sbOff = (r8 + (g8 >> 1) * 8) * KVS + (g8 & 1) * 8;
    const int vtOff = (r8 + (g8 >> 1) * 8) * KVS + (g8 & 1) * 8;

    unsigned aq[4][4];
#pragma unroll
    for (int ks = 0; ks < 4; ks++)
        ldsm4(aq[ks][0], aq[ks][1], aq[ks][2], aq[ks][3],
              pwB + (unsigned)(paOff + ks * 16) * 2u);

    float d[8][4];
#pragma unroll
    for (int j = 0; j < 8; j++)
#pragma unroll
        for (int r = 0; r < 4; r++) d[j][r] = 0.f;
    float M0 = -1e30f, M1 = -1e30f, L0 = 0.f, L1 = 0.f;

    const int mmode = mask_mode(mask);
    const size_t mb0 = ((size_t)b * SEQ + q0 + warp * 16 + gid) * SEQ;
    const size_t mb1 = mb0 + 8 * SEQ;
    const float L2E = 1.4426950408889634f;

    cp_wait<1>();
    __syncthreads();

    for (int kt = 0; kt < 16; kt++) {
        const int s = kt & 1;

        // ---- S = Q K^T ----
        float c[8][4];
#pragma unroll
        for (int j = 0; j < 8; j++)
#pragma unroll
            for (int r = 0; r < 4; r++) c[j][r] = 0.f;
#pragma unroll
        for (int ks = 0; ks < 4; ks++) {
            const int kc = ks * 16;
            unsigned bf[8][2];
#pragma unroll
            for (int jp = 0; jp < 4; jp++)
                ldsm4(bf[2*jp][0], bf[2*jp][1], bf[2*jp+1][0], bf[2*jp+1][1],
                      ksB[s] + (unsigned)(sbOff + jp * 16 * KVS + kc) * 2u);
#pragma unroll
            for (int j = 0; j < 8; j++)
                mma16(c[j][0], c[j][1], c[j][2], c[j][3],
                      aq[ks][0], aq[ks][1], aq[ks][2], aq[ks][3],
                      bf[j][0], bf[j][1]);
        }

        // ---- online softmax: 2^((c-M)*log2e) via f16x2 MUFU, P in regs ----
        float tm0 = -1e30f, tm1 = -1e30f;
#pragma unroll
        for (int j = 0; j < 8; j++) {
            tm0 = fmaxf(tm0, fmaxf(c[j][0], c[j][1]));
            tm1 = fmaxf(tm1, fmaxf(c[j][2], c[j][3]));
        }
        tm0 = fmaxf(tm0, __shfl_xor_sync(0xffffffffu, tm0, 1));
        tm0 = fmaxf(tm0, __shfl_xor_sync(0xffffffffu, tm0, 2));
        tm1 = fmaxf(tm1, __shfl_xor_sync(0xffffffffu, tm1, 1));
        tm1 = fmaxf(tm1, __shfl_xor_sync(0xffffffffu, tm1, 2));

        const float Mn0 = fmaxf(M0, tm0);
        const float Mn1 = fmaxf(M1, tm1);
        const float sc0 = __expf(M0 - Mn0);
        const float sc1 = __expf(M1 - Mn1);
        M0 = Mn0; M1 = Mn1;

        unsigned pA[8], pB[8];
        float s0 = 0.f, s1 = 0.f;
#pragma unroll
        for (int j = 0; j < 8; j++) {
            const int col = kt * 64 + j * 8 + 2 * tig;
            float e00 = mask_ok(mask, mmode, mb0 + col)     ? (c[j][0] - M0) * L2E : -100.f;
            float e01 = mask_ok(mask, mmode, mb0 + col + 1) ? (c[j][1] - M0) * L2E : -100.f;
            float e10 = mask_ok(mask, mmode, mb1 + col)     ? (c[j][2] - M1) * L2E : -100.f;
            float e11 = mask_ok(mask, mmode, mb1 + col + 1) ? (c[j][3] - M1) * L2E : -100.f;
            pA[j] = ex2h2(packh2f(e00, e01));
            pB[j] = ex2h2(packh2f(e10, e11));
            float2 f0 = __half22float2(*(__half2*)&pA[j]);
            float2 f1 = __half22float2(*(__half2*)&pB[j]);
            s0 += f0.x + f0.y;
            s1 += f1.x + f1.y;
        }
        s0 += __shfl_xor_sync(0xffffffffu, s0, 1);
        s0 += __shfl_xor_sync(0xffffffffu, s0, 2);
        s1 += __shfl_xor_sync(0xffffffffu, s1, 1);
        s1 += __shfl_xor_sync(0xffffffffu, s1, 2);
        L0 = L0 * sc0 + s0;
        L1 = L1 * sc1 + s1;
#pragma unroll
        for (int j = 0; j < 8; j++) {
            d[j][0] *= sc0; d[j][1] *= sc0;
            d[j][2] *= sc1; d[j][3] *= sc1;
        }

        // ---- O += P @ V ----
#pragma unroll
        for (int m = 0; m < 4; m++) {
            const int kc = m * 16;
            unsigned bf[8][2];
#pragma unroll
            for (int jp = 0; jp < 4; jp++)
                ldsm4t(bf[2*jp][0], bf[2*jp+1][0], bf[2*jp][1], bf[2*jp+1][1],
                       vsB[s] + (unsigned)(vtOff + kc * KVS + jp * 16) * 2u);
#pragma unroll
            for (int j = 0; j < 8; j++)
                mma16(d[j][0], d[j][1], d[j][2], d[j][3],
                      pA[2*m], pB[2*m], pA[2*m+1], pB[2*m+1],
                      bf[j][0], bf[j][1]);
        }

        __syncthreads();
        if (kt + 2 < 16) {
            issue(kt + 2, s);
            cp_wait<1>();
        } else {
            cp_wait<0>();
        }
        __syncthreads();
    }

    const float i0 = 1.0f / L0;
    const float i1 = 1.0f / L1;
    __half* O0 = CTX + baseo + (size_t)(q0 + warp * 16 + gid)     * DMODEL;
    __half* O1 = CTX + baseo + (size_t)(q0 + warp * 16 + gid + 8) * DMODEL;
#pragma unroll
    for (int j = 0; j < 8; j++) {
        const int col = j * 8 + 2 * tig;
        *(__half2*)(O0 + col) = __floats2half2_rn(d[j][0] * i0, d[j][1] * i0);
        *(__half2*)(O1 + col) = __floats2half2_rn(d[j][2] * i1, d[j][3] * i1);
    }
}

// ---------------------------------------------------------------------------
// Fused residual add + LayerNorm — single barrier, redundant final reduce
// ---------------------------------------------------------------------------
template <int WH>
__global__ void __launch_bounds__(256) add_ln_k(
    const float* __restrict__ A, const float* __restrict__ R,
    const float* __restrict__ g, const float* __restrict__ bta,
    float* __restrict__ O, __half* __restrict__ Oh)
{
    __shared__ float red[16];
    const int row = blockIdx.x;
    const int t   = threadIdx.x;
    const float* a = A + (size_t)row * DMODEL;
    const float* r = R + (size_t)row * DMODEL;

    float v[4];
    float s = 0.f, s2 = 0.f;
#pragma unroll
    for (int i = 0; i < 4; i++) {
        float x = a[t + 256 * i] + r[t + 256 * i];
        v[i] = x;
        s  += x;
        s2 += x * x;
    }
    const int lane = t & 31, wid = t >> 5;
#pragma unroll
    for (int o = 16; o > 0; o >>= 1) {
        s  += __shfl_xor_sync(0xffffffffu, s, o);
        s2 += __shfl_xor_sync(0xffffffffu, s2, o);
    }
    if (lane == 0) { red[wid] = s; red[8 + wid] = s2; }
    __syncthreads();
    float ts = 0.f, ts2 = 0.f;
#pragma unroll
    for (int i = 0; i < 8; i++) { ts += red[i]; ts2 += red[8 + i]; }
    const float mu  = ts * (1.0f / DMODEL);
    const float var = ts2 * (1.0f / DMODEL) - mu * mu;
    const float inv = rsqrtf(var + 1e-5f);

    float* o = O + (size_t)row * DMODEL;
#pragma unroll
    for (int i = 0; i < 4; i++) {
        int c = t + 256 * i;
        float y = (v[i] - mu) * inv * g[c] + bta[c];
        o[c] = y;
        if (WH) Oh[(size_t)row * DMODEL + c] = __float2half(y);
    }
}

// ---------------------------------------------------------------------------
// kernel_launch
// ---------------------------------------------------------------------------
extern "C" void kernel_launch(void* const* d_in, const int* in_sizes, int n_in,
                              void* d_out, int out_size)
{
    const float* X    = (const float*)d_in[0];
    const void*  mask = (const void*)d_in[1];
    const float* Wq   = (const float*)d_in[2];
    const float* Wk   = (const float*)d_in[3];
    const float* Wv   = (const float*)d_in[4];
    const float* Wo   = (const float*)d_in[5];
    const float* ln1g = (const float*)d_in[6];
    const float* ln1b = (const float*)d_in[7];
    const float* W1   = (const float*)d_in[8];
    const float* b1   = (const float*)d_in[9];
    const float* W2   = (const float*)d_in[10];
    const float* b2   = (const float*)d_in[11];
    const float* ln2g = (const float*)d_in[12];
    const float* ln2b = (const float*)d_in[13];
    float* out = (float*)d_out;

    __half *Xh, *QKVh, *CTXh, *X1h, *Hh;
    __half *WqkvTh, *WoTh, *W1Th, *W2Th;
    float *AO, *X1, *F;
    cudaGetSymbolAddress((void**)&Xh,     g_Xh);
    cudaGetSymbolAddress((void**)&QKVh,   g_QKVh);
    cudaGetSymbolAddress((void**)&CTXh,   g_CTXh);
    cudaGetSymbolAddress((void**)&X1h,    g_X1h);
    cudaGetSymbolAddress((void**)&Hh,     g_Hh);
    cudaGetSymbolAddress((void**)&AO,     g_AO);
    cudaGetSymbolAddress((void**)&X1,     g_X1);
    cudaGetSymbolAddress((void**)&F,      g_F);
    cudaGetSymbolAddress((void**)&WqkvTh, g_WqkvTh);
    cudaGetSymbolAddress((void**)&WoTh,   g_WoTh);
    cudaGetSymbolAddress((void**)&W1Th,   g_W1Th);
    cudaGetSymbolAddress((void**)&W2Th,   g_W2Th);

    cudaFuncSetAttribute(hgemm_k<0,1>, cudaFuncAttributeMaxDynamicSharedMemorySize, GEMM_SMEM);
    cudaFuncSetAttribute(hgemm_k<0,0>, cudaFuncAttributeMaxDynamicSharedMemorySize, GEMM_SMEM);
    cudaFuncSetAttribute(hgemm_k<2,1>, cudaFuncAttributeMaxDynamicSharedMemorySize, GEMM_SMEM);
    cudaFuncSetAttribute(hgemm_k<1,0>, cudaFuncAttributeMaxDynamicSharedMemorySize, GEMM_SMEM);
    cudaFuncSetAttribute(attn_k,       cudaFuncAttributeMaxDynamicSharedMemorySize, ATTN_SMEM);

    // Prep: launches ordered so attn_k is launch index 5 (ncu -s 5)
    f2h_k<<<(NROWS * DMODEL) / 1024, 256>>>(X, Xh, NROWS * DMODEL);        // 0
    {
        TPJobs J;                                                           // 1: Wq,Wk,Wv
        J.cnt = 3;
        const float* ins[3] = { Wq, Wk, Wv };
        int c = 0;
        for (int z = 0; z < 3; z++) {
            J.in[z] = ins[z];
            J.out[z] = WqkvTh + (size_t)z * DMODEL * DMODEL;
            J.K[z] = DMODEL; J.N[z] = DMODEL;
            c += (DMODEL / 64) * (DMODEL / 32);
            J.cum[z] = c;
        }
        transp_k<<<c, 256>>>(J);
    }
    {
        TPJobs J;                                                           // 2: Wo
        J.cnt = 1; J.in[0] = Wo; J.out[0] = WoTh; J.K[0] = DMODEL; J.N[0] = DMODEL;
        J.cum[0] = (DMODEL / 64) * (DMODEL / 32);
        transp_k<<<J.cum[0], 256>>>(J);
    }
    {
        TPJobs J;                                                           // 3: W1, W2
        J.cnt = 2;
        J.in[0] = W1; J.out[0] = W1Th; J.K[0] = DMODEL; J.N[0] = DFF;
        J.cum[0] = (DMODEL / 64) * (DFF / 32);
        J.in[1] = W2; J.out[1] = W2Th; J.K[1] = DFF; J.N[1] = DMODEL;
        J.cum[1] = J.cum[0] + (DFF / 64) * (DMODEL / 32);
        transp_k<<<J.cum[1], 256>>>(J);
    }

    const dim3 gQKV(QKVN / 128, NROWS / 128);   // (24, 64)
    const dim3 gD(DMODEL / 128, NROWS / 128);   // (8, 64)
    const dim3 gF(DFF / 128, NROWS / 128);      // (32, 64)

    // Fused QKV projection                                                 // 4
    hgemm_k<0,1><<<gQKV, 128, GEMM_SMEM>>>(Xh, WqkvTh, nullptr, QKVh, NROWS, QKVN, DMODEL);

    // Flash attention                                                      // 5
    attn_k<<<dim3(SEQ / 128, NHEAD, BATCH), 256, ATTN_SMEM>>>(QKVh, mask, CTXh);

    // Output projection (fp32 out)
    hgemm_k<0,0><<<gD, 128, GEMM_SMEM>>>(CTXh, WoTh, nullptr, AO, NROWS, DMODEL, DMODEL);

    // Residual + LN1 (dual write fp32 + fp16)
    add_ln_k<1><<<NROWS, 256>>>(AO, X, ln1g, ln1b, X1, X1h);

    // FFN
    hgemm_k<2,1><<<gF, 128, GEMM_SMEM>>>(X1h, W1Th, b1, Hh, NROWS, DFF, DMODEL);
    hgemm_k<1,0><<<gD, 128, GEMM_SMEM>>>(Hh, W2Th, b2, F, NROWS, DMODEL, DFF);

    // Residual + LN2 -> output
    add_ln_k<0><<<NROWS, 256>>>(F, X1, ln2g, ln2b, out, nullptr);
}

// round 13
// speedup vs baseline: 1.3929x; 1.3929x over previous
#include <cuda_runtime.h>
#include <cuda_fp16.h>
#include <cstdint>

#define BATCH   8
#define SEQ     1024
#define DMODEL  1024
#define NHEAD   16
#define HDIM    64
#define DFF     4096
#define NROWS   (BATCH * SEQ)           // 8192
#define QKVN    (3 * DMODEL)            // 3072

// ---------------------------------------------------------------------------
// Scratch buffers
// ---------------------------------------------------------------------------
__device__ __half g_Xh   [NROWS * DMODEL];
__device__ __half g_QKVh [NROWS * QKVN];
__device__ __half g_CTXh [NROWS * DMODEL];
__device__ __half g_X1h  [NROWS * DMODEL];
__device__ __half g_Hh   [NROWS * DFF];
__device__ float  g_AO   [NROWS * DMODEL];
__device__ float  g_X1   [NROWS * DMODEL];
__device__ float  g_F    [NROWS * DMODEL];
// transposed fp16 weights [N][K]
__device__ __half g_WqkvTh[QKVN * DMODEL];
__device__ __half g_WoTh  [DMODEL * DMODEL];
__device__ __half g_W1Th  [DFF * DMODEL];
__device__ __half g_W2Th  [DMODEL * DFF];

// ---------------------------------------------------------------------------
// Helpers
// ---------------------------------------------------------------------------
__device__ __forceinline__ unsigned smem_u32(const void* p) {
    return (unsigned)__cvta_generic_to_shared(p);
}
__device__ __forceinline__ void cp16(unsigned s, const void* g) {
    asm volatile("cp.async.cg.shared.global [%0], [%1], 16;" :: "r"(s), "l"(g));
}
__device__ __forceinline__ void cp_commit() {
    asm volatile("cp.async.commit_group;");
}
template <int N>
__device__ __forceinline__ void cp_wait() {
    asm volatile("cp.async.wait_group %0;" :: "n"(N));
}
__device__ __forceinline__ void mma16(
    float& c0, float& c1, float& c2, float& c3,
    unsigned a0, unsigned a1, unsigned a2, unsigned a3,
    unsigned b0, unsigned b1)
{
    asm volatile(
        "mma.sync.aligned.m16n8k16.row.col.f32.f16.f16.f32 "
        "{%0,%1,%2,%3},{%4,%5,%6,%7},{%8,%9},{%0,%1,%2,%3};"
        : "+f"(c0), "+f"(c1), "+f"(c2), "+f"(c3)
        : "r"(a0), "r"(a1), "r"(a2), "r"(a3), "r"(b0), "r"(b1));
}
__device__ __forceinline__ void ldsm4(
    unsigned& r0, unsigned& r1, unsigned& r2, unsigned& r3, unsigned addr)
{
    asm volatile("ldmatrix.sync.aligned.m8n8.x4.shared.b16 {%0,%1,%2,%3}, [%4];"
        : "=r"(r0), "=r"(r1), "=r"(r2), "=r"(r3) : "r"(addr));
}
__device__ __forceinline__ void ldsm4t(
    unsigned& r0, unsigned& r1, unsigned& r2, unsigned& r3, unsigned addr)
{
    asm volatile("ldmatrix.sync.aligned.m8n8.x4.trans.shared.b16 {%0,%1,%2,%3}, [%4];"
        : "=r"(r0), "=r"(r1), "=r"(r2), "=r"(r3) : "r"(addr));
}
__device__ __forceinline__ unsigned packh2(float a, float b) {
    __half2 h = __floats2half2_rn(a, b);
    return *(unsigned*)&h;
}

// ---------------------------------------------------------------------------
// Mask accessor
// ---------------------------------------------------------------------------
__device__ __forceinline__ int mask_mode(const void* mask) {
    unsigned w0 = *(const unsigned*)mask;
    return (w0 == 0x01010101u) ? 0 : 1;
}
__device__ __forceinline__ float mask_at(const void* mask, int mode, size_t idx) {
    if (mode == 0) return ((const unsigned char*)mask)[idx] ? 1.0f : 0.0f;
    return ((const unsigned*)mask)[idx] ? 1.0f : 0.0f;
}

// ---------------------------------------------------------------------------
// Prep kernels
// ---------------------------------------------------------------------------
__global__ void __launch_bounds__(256) f2h_k(
    const float* __restrict__ in, __half* __restrict__ out, int n)
{
    int i = (blockIdx.x * 256 + threadIdx.x) * 4;
    if (i < n) {
        float4 v = *(const float4*)(in + i);
        *(__half2*)(out + i)     = __floats2half2_rn(v.x, v.y);
        *(__half2*)(out + i + 2) = __floats2half2_rn(v.z, v.w);
    }
}

// up to 3 fused transposes per launch; 64(k) x 32(n) tile, half2 stores.
// out[n*K + k] = half(in[k*N + n])
struct TPJobs {
    const float* in[3];
    __half* out[3];
    int K[3], N[3], cum[3], cnt;
};
__global__ void __launch_bounds__(256) transp_k(TPJobs J)
{
    __shared__ float tile[64][33];
    int bid = blockIdx.x;
    int z = 0;
    while (z < J.cnt - 1 && bid >= J.cum[z]) z++;
    int lt = bid - (z ? J.cum[z - 1] : 0);
    const int K = J.K[z], N = J.N[z];
    const int ntk = K >> 6;                  // tiles along k
    const int kb = (lt % ntk) * 64;
    const int nb = (lt / ntk) * 32;
    const float* in = J.in[z];
    __half* out = J.out[z];
    const int tx = threadIdx.x & 31, wy = threadIdx.x >> 5;   // 32 x 8

#pragma unroll
    for (int i = wy; i < 64; i += 8)
        tile[i][tx] = in[(size_t)(kb + i) * N + nb + tx];
    __syncthreads();

#pragma unroll
    for (int p = 0; p < 4; p++) {
        const int n = wy + p * 8;
        __half2 v = __floats2half2_rn(tile[tx * 2][n], tile[tx * 2 + 1][n]);
        *(__half2*)(out + (size_t)(nb + n) * K + kb + tx * 2) = v;
    }
}

// ---------------------------------------------------------------------------
// fp16 GEMM, cp.async 2-stage, LDSM fragments: C = A @ Bt^T (+bias)(+relu)
// ---------------------------------------------------------------------------
#define TS 40
#define HSTAGE (128 * TS)
#define GEMM_SMEM (4 * HSTAGE * 2)    // 40960 B

template <int EPI, int OUTF>
__global__ void __launch_bounds__(128, 2) hgemm_k(
    const __half* __restrict__ A, const __half* __restrict__ Bt,
    const float* __restrict__ bias, void* __restrict__ Cv,
    int M, int N, int K)
{
    extern __shared__ __half hsm[];
    __half* Asm[2] = { hsm,              hsm + HSTAGE     };
    __half* Bsm[2] = { hsm + 2 * HSTAGE, hsm + 3 * HSTAGE };

    const int t    = threadIdx.x;
    const int lane = t & 31, warp = t >> 5;
    const int gid  = lane >> 2, tig = lane & 3;
    const int r8   = lane & 7,  g8  = lane >> 3;
    const int wm   = (warp & 1) * 64;
    const int wn   = (warp >> 1) * 64;
    const int bx   = blockIdx.x, by = blockIdx.y;

    const int lr = t >> 2, lch = (t & 3) * 8;

    const __half* Abase = A  + (size_t)(by * 128 + lr) * K + lch;
    const __half* Bbase = Bt + (size_t)(bx * 128 + lr) * K + lch;

    auto issue = [&](int kt, int s) {
        const __half* Ag = Abase + kt * 32;
        const __half* Bg = Bbase + kt * 32;
        __half* ad = Asm[s];
        __half* bd = Bsm[s];
#pragma unroll
        for (int p = 0; p < 4; p++) {
            cp16(smem_u32(&ad[(lr + p * 32) * TS + lch]), Ag + (size_t)(p * 32) * K);
            cp16(smem_u32(&bd[(lr + p * 32) * TS + lch]), Bg + (size_t)(p * 32) * K);
        }
        cp_commit();
    };

    const int aOff = (wm + r8 + (g8 & 1) * 8) * TS + (g8 >> 1) * 8;
    const int bOff = (wn + r8 + (g8 >> 1) * 8) * TS + (g8 & 1) * 8;
    const unsigned asB[2] = { smem_u32(Asm[0]), smem_u32(Asm[1]) };
    const unsigned bsB[2] = { smem_u32(Bsm[0]), smem_u32(Bsm[1]) };

    float acc[4][8][4];
#pragma unroll
    for (int i = 0; i < 4; i++)
#pragma unroll
        for (int j = 0; j < 8; j++)
#pragma unroll
            for (int r = 0; r < 4; r++) acc[i][j][r] = 0.f;

    const int nkt = K >> 5;
    issue(0, 0);
    issue(1, 1);
    cp_wait<1>();
    __syncthreads();

    for (int kt = 0; kt < nkt; ++kt) {
        const int s = kt & 1;
#pragma unroll
        for (int ks = 0; ks < 2; ++ks) {
            const int kc = ks * 16;
            unsigned af[4][4], bf[8][2];
#pragma unroll
            for (int i = 0; i < 4; i++)
                ldsm4(af[i][0], af[i][1], af[i][2], af[i][3],
                      asB[s] + (unsigned)(aOff + i * 16 * TS + kc) * 2u);
#pragma unroll
            for (int jp = 0; jp < 4; jp++)
                ldsm4(bf[2*jp][0], bf[2*jp][1], bf[2*jp+1][0], bf[2*jp+1][1],
                      bsB[s] + (unsigned)(bOff + jp * 16 * TS + kc) * 2u);
#pragma unroll
            for (int i = 0; i < 4; i++)
#pragma unroll
                for (int j = 0; j < 8; j++)
                    mma16(acc[i][j][0], acc[i][j][1], acc[i][j][2], acc[i][j][3],
                          af[i][0], af[i][1], af[i][2], af[i][3],
                          bf[j][0], bf[j][1]);
        }
        __syncthreads();
        if (kt + 2 < nkt) {
            issue(kt + 2, s);
            cp_wait<1>();
        } else {
            cp_wait<0>();
        }
        __syncthreads();
    }

#pragma unroll
    for (int i = 0; i < 4; i++) {
        const int r0 = by * 128 + wm + i * 16 + gid;
#pragma unroll
        for (int j = 0; j < 8; j++) {
            const int c0 = bx * 128 + wn + j * 8 + 2 * tig;
            float v0 = acc[i][j][0], v1 = acc[i][j][1];
            float v2 = acc[i][j][2], v3 = acc[i][j][3];
            if (EPI >= 1) {
                float b0 = bias[c0], b1 = bias[c0 + 1];
                v0 += b0; v1 += b1; v2 += b0; v3 += b1;
            }
            if (EPI == 2) {
                v0 = fmaxf(v0, 0.f); v1 = fmaxf(v1, 0.f);
                v2 = fmaxf(v2, 0.f); v3 = fmaxf(v3, 0.f);
            }
            if (OUTF == 1) {
                __half* C = (__half*)Cv;
                *(__half2*)(C + (size_t)r0 * N + c0)       = __floats2half2_rn(v0, v1);
                *(__half2*)(C + (size_t)(r0 + 8) * N + c0) = __floats2half2_rn(v2, v3);
            } else {
                float* C = (float*)Cv;
                *(float2*)(C + (size_t)r0 * N + c0)       = make_float2(v0, v1);
                *(float2*)(C + (size_t)(r0 + 8) * N + c0) = make_float2(v2, v3);
            }
        }
    }
}

// ---------------------------------------------------------------------------
// Flash attention (R11 version): fp16, 2-stage K/V, register-resident P,
// fp32 __expf softmax. Q/K/V in fused QKV buffer: Q@0, K@1024, V@2048.
// ---------------------------------------------------------------------------
#define KVS 72
#define KV_TILEH (64 * KVS)
#define ATTN_SMEM ((4 * KV_TILEH + 128 * KVS) * 2)       // 55296 B

__global__ void __launch_bounds__(256, 1) attn_k(
    const __half* __restrict__ QKV, const void* __restrict__ mask,
    __half* __restrict__ CTX)
{
    extern __shared__ __half smh[];
    __half* ksm[2] = { smh,                smh + KV_TILEH     };
    __half* vsm[2] = { smh + 2 * KV_TILEH, smh + 3 * KV_TILEH };
    __half* ps     = smh + 4 * KV_TILEH;

    const int qb = blockIdx.x, h = blockIdx.y, b = blockIdx.z;
    const int t = threadIdx.x, lane = t & 31, warp = t >> 5;
    const int gid = lane >> 2, tig = lane & 3;
    const int r8 = lane & 7, g8 = lane >> 3;
    const int q0 = qb * 128;
    const size_t baseq = (size_t)b * SEQ * QKVN + (size_t)h * HDIM;
    const size_t baseo = (size_t)b * SEQ * DMODEL + (size_t)h * HDIM;

    const int lr = t >> 3;
    const int lch = (t & 7) * 8;

    auto issue = [&](int kt, int s) {
        const __half* Kg = QKV + baseq + DMODEL     + (size_t)(kt * 64) * QKVN;
        const __half* Vg = QKV + baseq + 2 * DMODEL + (size_t)(kt * 64) * QKVN;
        __half* kd = ksm[s];
        __half* vd = vsm[s];
#pragma unroll
        for (int p = 0; p < 2; p++) {
            int r = p * 32 + lr;
            cp16(smem_u32(&kd[r * KVS + lch]), Kg + (size_t)r * QKVN + lch);
            cp16(smem_u32(&vd[r * KVS + lch]), Vg + (size_t)r * QKVN + lch);
        }
        cp_commit();
    };

    issue(0, 0);
    issue(1, 1);

    __half* pw = ps + warp * 16 * KVS;
    {
        const int row = lane >> 1;
        const int colh = (lane & 1) * 32;
        const uint4* qg4 = (const uint4*)(QKV + baseq + (size_t)(q0 + warp * 16 + row) * QKVN + colh);
        uint4* qp4 = (uint4*)(pw + row * KVS + colh);
#pragma unroll
        for (int i = 0; i < 4; i++) qp4[i] = qg4[i];
    }
    __syncwarp();

    const unsigned pwB = smem_u32(pw);
    const unsigned ksB[2] = { smem_u32(ksm[0]), smem_u32(ksm[1]) };
    const unsigned vsB[2] = { smem_u32(vsm[0]), smem_u32(vsm[1]) };
    const int paOff = (r8 + (g8 & 1) * 8) * KVS + (g8 >> 1) * 8;
    const int sbOff = (r8 + (g8 >> 1) * 8) * KVS + (g8 & 1) * 8;
    const int vtOff = (r8 + (g8 >> 1) * 8) * KVS + (g8 & 1) * 8;

    unsigned aq[4][4];
#pragma unroll
    for (int ks = 0; ks < 4; ks++)
        ldsm4(aq[ks][0], aq[ks][1], aq[ks][2], aq[ks][3],
              pwB + (unsigned)(paOff + ks * 16) * 2u);

    float d[8][4];
#pragma unroll
    for (int j = 0; j < 8; j++)
#pragma unroll
        for (int r = 0; r < 4; r++) d[j][r] = 0.f;
    float M0 = -1e30f, M1 = -1e30f, L0 = 0.f, L1 = 0.f;

    const int mmode = mask_mode(mask);
    const size_t mb0 = ((size_t)b * SEQ + q0 + warp * 16 + gid) * SEQ;
    const size_t mb1 = mb0 + 8 * SEQ;

    cp_wait<1>();
    __syncthreads();

    for (int kt = 0; kt < 16; kt++) {
        const int s = kt & 1;

        // ---- S = Q K^T ----
        float c[8][4];
#pragma unroll
        for (int j = 0; j < 8; j++)
#pragma unroll
            for (int r = 0; r < 4; r++) c[j][r] = 0.f;
#pragma unroll
        for (int ks = 0; ks < 4; ks++) {
            const int kc = ks * 16;
            unsigned bf[8][2];
#pragma unroll
            for (int jp = 0; jp < 4; jp++)
                ldsm4(bf[2*jp][0], bf[2*jp][1], bf[2*jp+1][0], bf[2*jp+1][1],
                      ksB[s] + (unsigned)(sbOff + jp * 16 * KVS + kc) * 2u);
#pragma unroll
            for (int j = 0; j < 8; j++)
                mma16(c[j][0], c[j][1], c[j][2], c[j][3],
                      aq[ks][0], aq[ks][1], aq[ks][2], aq[ks][3],
                      bf[j][0], bf[j][1]);
        }

        // ---- online softmax (fp32 exp, P packed into registers) ----
        float tm0 = -1e30f, tm1 = -1e30f;
#pragma unroll
        for (int j = 0; j < 8; j++) {
            tm0 = fmaxf(tm0, fmaxf(c[j][0], c[j][1]));
            tm1 = fmaxf(tm1, fmaxf(c[j][2], c[j][3]));
        }
        tm0 = fmaxf(tm0, __shfl_xor_sync(0xffffffffu, tm0, 1));
        tm0 = fmaxf(tm0, __shfl_xor_sync(0xffffffffu, tm0, 2));
        tm1 = fmaxf(tm1, __shfl_xor_sync(0xffffffffu, tm1, 1));
        tm1 = fmaxf(tm1, __shfl_xor_sync(0xffffffffu, tm1, 2));

        const float Mn0 = fmaxf(M0, tm0);
        const float Mn1 = fmaxf(M1, tm1);
        const float sc0 = __expf(M0 - Mn0);
        const float sc1 = __expf(M1 - Mn1);
        M0 = Mn0; M1 = Mn1;

        unsigned pA[8], pB[8];
        float s0 = 0.f, s1 = 0.f;
#pragma unroll
        for (int j = 0; j < 8; j++) {
            const int col = kt * 64 + j * 8 + 2 * tig;
            float p00 = __expf(c[j][0] - M0) * mask_at(mask, mmode, mb0 + col);
            float p01 = __expf(c[j][1] - M0) * mask_at(mask, mmode, mb0 + col + 1);
            float p10 = __expf(c[j][2] - M1) * mask_at(mask, mmode, mb1 + col);
            float p11 = __expf(c[j][3] - M1) * mask_at(mask, mmode, mb1 + col + 1);
            s0 += p00 + p01;
            s1 += p10 + p11;
            pA[j] = packh2(p00, p01);
            pB[j] = packh2(p10, p11);
        }
        s0 += __shfl_xor_sync(0xffffffffu, s0, 1);
        s0 += __shfl_xor_sync(0xffffffffu, s0, 2);
        s1 += __shfl_xor_sync(0xffffffffu, s1, 1);
        s1 += __shfl_xor_sync(0xffffffffu, s1, 2);
        L0 = L0 * sc0 + s0;
        L1 = L1 * sc1 + s1;
#pragma unroll
        for (int j = 0; j < 8; j++) {
            d[j][0] *= sc0; d[j][1] *= sc0;
            d[j][2] *= sc1; d[j][3] *= sc1;
        }

        // ---- O += P @ V ----
#pragma unroll
        for (int m = 0; m < 4; m++) {
            const int kc = m * 16;
            unsigned bf[8][2];
#pragma unroll
            for (int jp = 0; jp < 4; jp++)
                ldsm4t(bf[2*jp][0], bf[2*jp+1][0], bf[2*jp][1], bf[2*jp+1][1],
                       vsB[s] + (unsigned)(vtOff + kc * KVS + jp * 16) * 2u);
#pragma unroll
            for (int j = 0; j < 8; j++)
                mma16(d[j][0], d[j][1], d[j][2], d[j][3],
                      pA[2*m], pB[2*m], pA[2*m+1], pB[2*m+1],
                      bf[j][0], bf[j][1]);
        }

        __syncthreads();
        if (kt + 2 < 16) {
            issue(kt + 2, s);
            cp_wait<1>();
        } else {
            cp_wait<0>();
        }
        __syncthreads();
    }

    const float i0 = 1.0f / L0;
    const float i1 = 1.0f / L1;
    __half* O0 = CTX + baseo + (size_t)(q0 + warp * 16 + gid)     * DMODEL;
    __half* O1 = CTX + baseo + (size_t)(q0 + warp * 16 + gid + 8) * DMODEL;
#pragma unroll
    for (int j = 0; j < 8; j++) {
        const int col = j * 8 + 2 * tig;
        *(__half2*)(O0 + col) = __floats2half2_rn(d[j][0] * i0, d[j][1] * i0);
        *(__half2*)(O1 + col) = __floats2half2_rn(d[j][2] * i1, d[j][3] * i1);
    }
}

// ---------------------------------------------------------------------------
// Fused residual add + LayerNorm — single barrier, redundant final reduce
// ---------------------------------------------------------------------------
template <int WH>
__global__ void __launch_bounds__(256) add_ln_k(
    const float* __restrict__ A, const float* __restrict__ R,
    const float* __restrict__ g, const float* __restrict__ bta,
    float* __restrict__ O, __half* __restrict__ Oh)
{
    __shared__ float red[16];
    const int row = blockIdx.x;
    const int t   = threadIdx.x;
    const float* a = A + (size_t)row * DMODEL;
    const float* r = R + (size_t)row * DMODEL;

    float v[4];
    float s = 0.f, s2 = 0.f;
#pragma unroll
    for (int i = 0; i < 4; i++) {
        float x = a[t + 256 * i] + r[t + 256 * i];
        v[i] = x;
        s  += x;
        s2 += x * x;
    }
    const int lane = t & 31, wid = t >> 5;
#pragma unroll
    for (int o = 16; o > 0; o >>= 1) {
        s  += __shfl_xor_sync(0xffffffffu, s, o);
        s2 += __shfl_xor_sync(0xffffffffu, s2, o);
    }
    if (lane == 0) { red[wid] = s; red[8 + wid] = s2; }
    __syncthreads();
    float ts = 0.f, ts2 = 0.f;
#pragma unroll
    for (int i = 0; i < 8; i++) { ts += red[i]; ts2 += red[8 + i]; }
    const float mu  = ts * (1.0f / DMODEL);
    const float var = ts2 * (1.0f / DMODEL) - mu * mu;
    const float inv = rsqrtf(var + 1e-5f);

    float* o = O + (size_t)row * DMODEL;
#pragma unroll
    for (int i = 0; i < 4; i++) {
        int c = t + 256 * i;
        float y = (v[i] - mu) * inv * g[c] + bta[c];
        o[c] = y;
        if (WH) Oh[(size_t)row * DMODEL + c] = __float2half(y);
    }
}

// ---------------------------------------------------------------------------
// kernel_launch
// ---------------------------------------------------------------------------
extern "C" void kernel_launch(void* const* d_in, const int* in_sizes, int n_in,
                              void* d_out, int out_size)
{
    const float* X    = (const float*)d_in[0];
    const void*  mask = (const void*)d_in[1];
    const float* Wq   = (const float*)d_in[2];
    const float* Wk   = (const float*)d_in[3];
    const float* Wv   = (const float*)d_in[4];
    const float* Wo   = (const float*)d_in[5];
    const float* ln1g = (const float*)d_in[6];
    const float* ln1b = (const float*)d_in[7];
    const float* W1   = (const float*)d_in[8];
    const float* b1   = (const float*)d_in[9];
    const float* W2   = (const float*)d_in[10];
    const float* b2   = (const float*)d_in[11];
    const float* ln2g = (const float*)d_in[12];
    const float* ln2b = (const float*)d_in[13];
    float* out = (float*)d_out;

    __half *Xh, *QKVh, *CTXh, *X1h, *Hh;
    __half *WqkvTh, *WoTh, *W1Th, *W2Th;
    float *AO, *X1, *F;
    cudaGetSymbolAddress((void**)&Xh,     g_Xh);
    cudaGetSymbolAddress((void**)&QKVh,   g_QKVh);
    cudaGetSymbolAddress((void**)&CTXh,   g_CTXh);
    cudaGetSymbolAddress((void**)&X1h,    g_X1h);
    cudaGetSymbolAddress((void**)&Hh,     g_Hh);
    cudaGetSymbolAddress((void**)&AO,     g_AO);
    cudaGetSymbolAddress((void**)&X1,     g_X1);
    cudaGetSymbolAddress((void**)&F,      g_F);
    cudaGetSymbolAddress((void**)&WqkvTh, g_WqkvTh);
    cudaGetSymbolAddress((void**)&WoTh,   g_WoTh);
    cudaGetSymbolAddress((void**)&W1Th,   g_W1Th);
    cudaGetSymbolAddress((void**)&W2Th,   g_W2Th);

    cudaFuncSetAttribute(hgemm_k<0,1>, cudaFuncAttributeMaxDynamicSharedMemorySize, GEMM_SMEM);
    cudaFuncSetAttribute(hgemm_k<0,0>, cudaFuncAttributeMaxDynamicSharedMemorySize, GEMM_SMEM);
    cudaFuncSetAttribute(hgemm_k<2,1>, cudaFuncAttributeMaxDynamicSharedMemorySize, GEMM_SMEM);
    cudaFuncSetAttribute(hgemm_k<1,0>, cudaFuncAttributeMaxDynamicSharedMemorySize, GEMM_SMEM);
    cudaFuncSetAttribute(attn_k,       cudaFuncAttributeMaxDynamicSharedMemorySize, ATTN_SMEM);

    // Prep: launches ordered so attn_k is launch index 5 (ncu -s 5)
    f2h_k<<<(NROWS * DMODEL) / 1024, 256>>>(X, Xh, NROWS * DMODEL);        // 0
    {
        TPJobs J;                                                           // 1: Wq,Wk,Wv
        J.cnt = 3;
        const float* ins[3] = { Wq, Wk, Wv };
        int c = 0;
        for (int z = 0; z < 3; z++) {
            J.in[z] = ins[z];
            J.out[z] = WqkvTh + (size_t)z * DMODEL * DMODEL;
            J.K[z] = DMODEL; J.N[z] = DMODEL;
            c += (DMODEL / 64) * (DMODEL / 32);
            J.cum[z] = c;
        }
        transp_k<<<c, 256>>>(J);
    }
    {
        TPJobs J;                                                           // 2: Wo
        J.cnt = 1; J.in[0] = Wo; J.out[0] = WoTh; J.K[0] = DMODEL; J.N[0] = DMODEL;
        J.cum[0] = (DMODEL / 64) * (DMODEL / 32);
        transp_k<<<J.cum[0], 256>>>(J);
    }
    {
        TPJobs J;                                                           // 3: W1, W2
        J.cnt = 2;
        J.in[0] = W1; J.out[0] = W1Th; J.K[0] = DMODEL; J.N[0] = DFF;
        J.cum[0] = (DMODEL / 64) * (DFF / 32);
        J.in[1] = W2; J.out[1] = W2Th; J.K[1] = DFF; J.N[1] = DMODEL;
        J.cum[1] = J.cum[0] + (DFF / 64) * (DMODEL / 32);
        transp_k<<<J.cum[1], 256>>>(J);
    }

    const dim3 gQKV(QKVN / 128, NROWS / 128);   // (24, 64)
    const dim3 gD(DMODEL / 128, NROWS / 128);   // (8, 64)
    const dim3 gF(DFF / 128, NROWS / 128);      // (32, 64)

    // Fused QKV projection                                                 // 4
    hgemm_k<0,1><<<gQKV, 128, GEMM_SMEM>>>(Xh, WqkvTh, nullptr, QKVh, NROWS, QKVN, DMODEL);

    // Flash attention                                                      // 5
    attn_k<<<dim3(SEQ / 128, NHEAD, BATCH), 256, ATTN_SMEM>>>(QKVh, mask, CTXh);

    // Output projection (fp32 out)
    hgemm_k<0,0><<<gD, 128, GEMM_SMEM>>>(CTXh, WoTh, nullptr, AO, NROWS, DMODEL, DMODEL);

    // Residual + LN1 (dual write fp32 + fp16)
    add_ln_k<1><<<NROWS, 256>>>(AO, X, ln1g, ln1b, X1, X1h);

    // FFN
    hgemm_k<2,1><<<gF, 128, GEMM_SMEM>>>(X1h, W1Th, b1, Hh, NROWS, DFF, DMODEL);
    hgemm_k<1,0><<<gD, 128, GEMM_SMEM>>>(Hh, W2Th, b2, F, NROWS, DMODEL, DFF);

    // Residual + LN2 -> output
    add_ln_k<0><<<NROWS, 256>>>(F, X1, ln2g, ln2b, out, nullptr);
}

// round 15
// speedup vs baseline: 1.4731x; 1.0575x over previous
#include <cuda_runtime.h>
#include <cuda_fp16.h>
#include <cstdint>

#define BATCH   8
#define SEQ     1024
#define DMODEL  1024
#define NHEAD   16
#define HDIM    64
#define DFF     4096
#define NROWS   (BATCH * SEQ)           // 8192
#define QKVN    (3 * DMODEL)            // 3072
#define MBWORDS (BATCH * SEQ * SEQ / 32)  // 262144

// ---------------------------------------------------------------------------
// Scratch buffers
// ---------------------------------------------------------------------------
__device__ __half g_Xh   [NROWS * DMODEL];
__device__ __half g_QKVh [NROWS * QKVN];
__device__ __half g_CTXh [NROWS * DMODEL];
__device__ __half g_X1h  [NROWS * DMODEL];
__device__ __half g_Hh   [NROWS * DFF];
__device__ float  g_AO   [NROWS * DMODEL];
__device__ float  g_X1   [NROWS * DMODEL];
__device__ float  g_F    [NROWS * DMODEL];
__device__ unsigned g_MB [MBWORDS];       // bit-packed mask
// transposed fp16 weights [N][K]
__device__ __half g_WqkvTh[QKVN * DMODEL];
__device__ __half g_WoTh  [DMODEL * DMODEL];
__device__ __half g_W1Th  [DFF * DMODEL];
__device__ __half g_W2Th  [DMODEL * DFF];

// ---------------------------------------------------------------------------
// Helpers
// ---------------------------------------------------------------------------
__device__ __forceinline__ unsigned smem_u32(const void* p) {
    return (unsigned)__cvta_generic_to_shared(p);
}
__device__ __forceinline__ void cp16(unsigned s, const void* g) {
    asm volatile("cp.async.cg.shared.global [%0], [%1], 16;" :: "r"(s), "l"(g));
}
__device__ __forceinline__ void cp_commit() {
    asm volatile("cp.async.commit_group;");
}
template <int N>
__device__ __forceinline__ void cp_wait() {
    asm volatile("cp.async.wait_group %0;" :: "n"(N));
}
__device__ __forceinline__ void mma16(
    float& c0, float& c1, float& c2, float& c3,
    unsigned a0, unsigned a1, unsigned a2, unsigned a3,
    unsigned b0, unsigned b1)
{
    asm volatile(
        "mma.sync.aligned.m16n8k16.row.col.f32.f16.f16.f32 "
        "{%0,%1,%2,%3},{%4,%5,%6,%7},{%8,%9},{%0,%1,%2,%3};"
        : "+f"(c0), "+f"(c1), "+f"(c2), "+f"(c3)
        : "r"(a0), "r"(a1), "r"(a2), "r"(a3), "r"(b0), "r"(b1));
}
__device__ __forceinline__ void ldsm4(
    unsigned& r0, unsigned& r1, unsigned& r2, unsigned& r3, unsigned addr)
{
    asm volatile("ldmatrix.sync.aligned.m8n8.x4.shared.b16 {%0,%1,%2,%3}, [%4];"
        : "=r"(r0), "=r"(r1), "=r"(r2), "=r"(r3) : "r"(addr));
}
__device__ __forceinline__ void ldsm4t(
    unsigned& r0, unsigned& r1, unsigned& r2, unsigned& r3, unsigned addr)
{
    asm volatile("ldmatrix.sync.aligned.m8n8.x4.trans.shared.b16 {%0,%1,%2,%3}, [%4];"
        : "=r"(r0), "=r"(r1), "=r"(r2), "=r"(r3) : "r"(addr));
}
__device__ __forceinline__ unsigned packh2(float a, float b) {
    __half2 h = __floats2half2_rn(a, b);
    return *(unsigned*)&h;
}

// ---------------------------------------------------------------------------
// Mask handling: detect element width once, bit-pack into g_MB
// ---------------------------------------------------------------------------
__device__ __forceinline__ int mask_mode(const void* mask) {
    unsigned w0 = *(const unsigned*)mask;
    return (w0 == 0x01010101u) ? 0 : 1;   // 0 = u8, 1 = u32 elems
}
__global__ void __launch_bounds__(256) maskpack_k(
    const void* __restrict__ mask, unsigned* __restrict__ out)
{
    const int mode = mask_mode(mask);
    const size_t i = (size_t)blockIdx.x * 256 + threadIdx.x;   // one word
    unsigned w = 0;
    if (mode == 0) {
        const unsigned char* m = (const unsigned char*)mask + i * 32;
#pragma unroll
        for (int b = 0; b < 32; b++) w |= (m[b] ? 1u : 0u) << b;
    } else {
        const unsigned* m = (const unsigned*)mask + i * 32;
#pragma unroll
        for (int b = 0; b < 32; b++) w |= (m[b] ? 1u : 0u) << b;
    }
    out[i] = w;
}

// ---------------------------------------------------------------------------
// Prep kernels
// ---------------------------------------------------------------------------
__global__ void __launch_bounds__(256) f2h_k(
    const float* __restrict__ in, __half* __restrict__ out, int n)
{
    int i = (blockIdx.x * 256 + threadIdx.x) * 4;
    if (i < n) {
        float4 v = *(const float4*)(in + i);
        *(__half2*)(out + i)     = __floats2half2_rn(v.x, v.y);
        *(__half2*)(out + i + 2) = __floats2half2_rn(v.z, v.w);
    }
}

// up to 3 fused transposes per launch; 64(k) x 32(n) tile, half2 stores.
struct TPJobs {
    const float* in[3];
    __half* out[3];
    int K[3], N[3], cum[3], cnt;
};
__global__ void __launch_bounds__(256) transp_k(TPJobs J)
{
    __shared__ float tile[64][33];
    int bid = blockIdx.x;
    int z = 0;
    while (z < J.cnt - 1 && bid >= J.cum[z]) z++;
    int lt = bid - (z ? J.cum[z - 1] : 0);
    const int K = J.K[z], N = J.N[z];
    const int ntk = K >> 6;
    const int kb = (lt % ntk) * 64;
    const int nb = (lt / ntk) * 32;
    const float* in = J.in[z];
    __half* out = J.out[z];
    const int tx = threadIdx.x & 31, wy = threadIdx.x >> 5;

#pragma unroll
    for (int i = wy; i < 64; i += 8)
        tile[i][tx] = in[(size_t)(kb + i) * N + nb + tx];
    __syncthreads();

#pragma unroll
    for (int p = 0; p < 4; p++) {
        const int n = wy + p * 8;
        __half2 v = __floats2half2_rn(tile[tx * 2][n], tile[tx * 2 + 1][n]);
        *(__half2*)(out + (size_t)(nb + n) * K + kb + tx * 2) = v;
    }
}

// ---------------------------------------------------------------------------
// fp16 GEMM, cp.async 2-stage, LDSM fragments: C = A @ Bt^T (+bias)(+relu)
// ---------------------------------------------------------------------------
#define TS 40
#define HSTAGE (128 * TS)
#define GEMM_SMEM (4 * HSTAGE * 2)    // 40960 B

template <int EPI, int OUTF>
__global__ void __launch_bounds__(128, 2) hgemm_k(
    const __half* __restrict__ A, const __half* __restrict__ Bt,
    const float* __restrict__ bias, void* __restrict__ Cv,
    int M, int N, int K)
{
    extern __shared__ __half hsm[];
    __half* Asm[2] = { hsm,              hsm + HSTAGE     };
    __half* Bsm[2] = { hsm + 2 * HSTAGE, hsm + 3 * HSTAGE };

    const int t    = threadIdx.x;
    const int lane = t & 31, warp = t >> 5;
    const int gid  = lane >> 2, tig = lane & 3;
    const int r8   = lane & 7,  g8  = lane >> 3;
    const int wm   = (warp & 1) * 64;
    const int wn   = (warp >> 1) * 64;
    const int bx   = blockIdx.x, by = blockIdx.y;

    const int lr = t >> 2, lch = (t & 3) * 8;

    const __half* Abase = A  + (size_t)(by * 128 + lr) * K + lch;
    const __half* Bbase = Bt + (size_t)(bx * 128 + lr) * K + lch;

    auto issue = [&](int kt, int s) {
        const __half* Ag = Abase + kt * 32;
        const __half* Bg = Bbase + kt * 32;
        __half* ad = Asm[s];
        __half* bd = Bsm[s];
#pragma unroll
        for (int p = 0; p < 4; p++) {
            cp16(smem_u32(&ad[(lr + p * 32) * TS + lch]), Ag + (size_t)(p * 32) * K);
            cp16(smem_u32(&bd[(lr + p * 32) * TS + lch]), Bg + (size_t)(p * 32) * K);
        }
        cp_commit();
    };

    const int aOff = (wm + r8 + (g8 & 1) * 8) * TS + (g8 >> 1) * 8;
    const int bOff = (wn + r8 + (g8 >> 1) * 8) * TS + (g8 & 1) * 8;
    const unsigned asB[2] = { smem_u32(Asm[0]), smem_u32(Asm[1]) };
    const unsigned bsB[2] = { smem_u32(Bsm[0]), smem_u32(Bsm[1]) };

    float acc[4][8][4];
#pragma unroll
    for (int i = 0; i < 4; i++)
#pragma unroll
        for (int j = 0; j < 8; j++)
#pragma unroll
            for (int r = 0; r < 4; r++) acc[i][j][r] = 0.f;

    const int nkt = K >> 5;
    issue(0, 0);
    issue(1, 1);
    cp_wait<1>();
    __syncthreads();

    for (int kt = 0; kt < nkt; ++kt) {
        const int s = kt & 1;
#pragma unroll
        for (int ks = 0; ks < 2; ++ks) {
            const int kc = ks * 16;
            unsigned af[4][4], bf[8][2];
#pragma unroll
            for (int i = 0; i < 4; i++)
                ldsm4(af[i][0], af[i][1], af[i][2], af[i][3],
                      asB[s] + (unsigned)(aOff + i * 16 * TS + kc) * 2u);
#pragma unroll
            for (int jp = 0; jp < 4; jp++)
                ldsm4(bf[2*jp][0], bf[2*jp][1], bf[2*jp+1][0], bf[2*jp+1][1],
                      bsB[s] + (unsigned)(bOff + jp * 16 * TS + kc) * 2u);
#pragma unroll
            for (int i = 0; i < 4; i++)
#pragma unroll
                for (int j = 0; j < 8; j++)
                    mma16(acc[i][j][0], acc[i][j][1], acc[i][j][2], acc[i][j][3],
                          af[i][0], af[i][1], af[i][2], af[i][3],
                          bf[j][0], bf[j][1]);
        }
        __syncthreads();
        if (kt + 2 < nkt) {
            issue(kt + 2, s);
            cp_wait<1>();
        } else {
            cp_wait<0>();
        }
        __syncthreads();
    }

#pragma unroll
    for (int i = 0; i < 4; i++) {
        const int r0 = by * 128 + wm + i * 16 + gid;
#pragma unroll
        for (int j = 0; j < 8; j++) {
            const int c0 = bx * 128 + wn + j * 8 + 2 * tig;
            float v0 = acc[i][j][0], v1 = acc[i][j][1];
            float v2 = acc[i][j][2], v3 = acc[i][j][3];
            if (EPI >= 1) {
                float b0 = bias[c0], b1 = bias[c0 + 1];
                v0 += b0; v1 += b1; v2 += b0; v3 += b1;
            }
            if (EPI == 2) {
                v0 = fmaxf(v0, 0.f); v1 = fmaxf(v1, 0.f);
                v2 = fmaxf(v2, 0.f); v3 = fmaxf(v3, 0.f);
            }
            if (OUTF == 1) {
                __half* C = (__half*)Cv;
                *(__half2*)(C + (size_t)r0 * N + c0)       = __floats2half2_rn(v0, v1);
                *(__half2*)(C + (size_t)(r0 + 8) * N + c0) = __floats2half2_rn(v2, v3);
            } else {
                float* C = (float*)Cv;
                *(float2*)(C + (size_t)r0 * N + c0)       = make_float2(v0, v1);
                *(float2*)(C + (size_t)(r0 + 8) * N + c0) = make_float2(v2, v3);
            }
        }
    }
}

// ---------------------------------------------------------------------------
// Flash attention: fp16, 2-stage K/V, register P, bit-packed mask.
// Q/K/V in fused QKV buffer [NROWS][3072]: Q@0, K@1024, V@2048.
// ---------------------------------------------------------------------------
#define KVS 72
#define KV_TILEH (64 * KVS)
#define ATTN_SMEM ((4 * KV_TILEH + 128 * KVS) * 2)       // 55296 B

__global__ void __launch_bounds__(256, 1) attn_k(
    const __half* __restrict__ QKV, const unsigned* __restrict__ MB,
    __half* __restrict__ CTX)
{
    extern __shared__ __half smh[];
    __half* ksm[2] = { smh,                smh + KV_TILEH     };
    __half* vsm[2] = { smh + 2 * KV_TILEH, smh + 3 * KV_TILEH };
    __half* ps     = smh + 4 * KV_TILEH;

    const int qb = blockIdx.x, h = blockIdx.y, b = blockIdx.z;
    const int t = threadIdx.x, lane = t & 31, warp = t >> 5;
    const int gid = lane >> 2, tig = lane & 3;
    const int r8 = lane & 7, g8 = lane >> 3;
    const int q0 = qb * 128;
    const size_t baseq = (size_t)b * SEQ * QKVN + (size_t)h * HDIM;
    const size_t baseo = (size_t)b * SEQ * DMODEL + (size_t)h * HDIM;

    const int lr = t >> 3;
    const int lch = (t & 7) * 8;

    auto issue = [&](int kt, int s) {
        const __half* Kg = QKV + baseq + DMODEL     + (size_t)(kt * 64) * QKVN;
        const __half* Vg = QKV + baseq + 2 * DMODEL + (size_t)(kt * 64) * QKVN;
        __half* kd = ksm[s];
        __half* vd = vsm[s];
#pragma unroll
        for (int p = 0; p < 2; p++) {
            int r = p * 32 + lr;
            cp16(smem_u32(&kd[r * KVS + lch]), Kg + (size_t)r * QKVN + lch);
            cp16(smem_u32(&vd[r * KVS + lch]), Vg + (size_t)r * QKVN + lch);
        }
        cp_commit();
    };

    issue(0, 0);
    issue(1, 1);

    __half* pw = ps + warp * 16 * KVS;
    {
        const int row = lane >> 1;
        const int colh = (lane & 1) * 32;
        const uint4* qg4 = (const uint4*)(QKV + baseq + (size_t)(q0 + warp * 16 + row) * QKVN + colh);
        uint4* qp4 = (uint4*)(pw + row * KVS + colh);
#pragma unroll
        for (int i = 0; i < 4; i++) qp4[i] = qg4[i];
    }
    __syncwarp();

    const unsigned pwB = smem_u32(pw);
    const unsigned ksB[2] = { smem_u32(ksm[0]), smem_u32(ksm[1]) };
    const unsigned vsB[2] = { smem_u32(vsm[0]), smem_u32(vsm[1]) };
    const int paOff = (r8 + (g8 & 1) * 8) * KVS + (g8 >> 1) * 8;
    const int sbOff = (r8 + (g8 >> 1) * 8) * KVS + (g8 & 1) * 8;
    const int vtOff = (r8 + (g8 >> 1) * 8) * KVS + (g8 & 1) * 8;

    unsigned aq[4][4];
#pragma unroll
    for (int ks = 0; ks < 4; ks++)
        ldsm4(aq[ks][0], aq[ks][1], aq[ks][2], aq[ks][3],
              pwB + (unsigned)(paOff + ks * 16) * 2u);

    float d[8][4];
#pragma unroll
    for (int j = 0; j < 8; j++)
#pragma unroll
        for (int r = 0; r < 4; r++) d[j][r] = 0.f;
    float M0 = -1e30f, M1 = -1e30f, L0 = 0.f, L1 = 0.f;

    // bit-packed mask row bases (u32-word units; 32 words per row)
    const size_t mw0 = ((size_t)b * SEQ + q0 + warp * 16 + gid) * 32;
    const size_t mw1 = mw0 + 8 * 32;

    cp_wait<1>();
    __syncthreads();

    for (int kt = 0; kt < 16; kt++) {
        const int s = kt & 1;

        // mask words for this 64-key tile (2 words per row)
        const unsigned m00 = MB[mw0 + kt * 2], m01 = MB[mw0 + kt * 2 + 1];
        const unsigned m10 = MB[mw1 + kt * 2], m11 = MB[mw1 + kt * 2 + 1];

        // ---- S = Q K^T ----
        float c[8][4];
#pragma unroll
        for (int j = 0; j < 8; j++)
#pragma unroll
            for (int r = 0; r < 4; r++) c[j][r] = 0.f;
#pragma unroll
        for (int ks = 0; ks < 4; ks++) {
            const int kc = ks * 16;
            unsigned bf[8][2];
#pragma unroll
            for (int jp = 0; jp < 4; jp++)
                ldsm4(bf[2*jp][0], bf[2*jp][1], bf[2*jp+1][0], bf[2*jp+1][1],
                      ksB[s] + (unsigned)(sbOff + jp * 16 * KVS + kc) * 2u);
#pragma unroll
            for (int j = 0; j < 8; j++)
                mma16(c[j][0], c[j][1], c[j][2], c[j][3],
                      aq[ks][0], aq[ks][1], aq[ks][2], aq[ks][3],
                      bf[j][0], bf[j][1]);
        }

        // ---- online softmax (fp32 exp, P packed into registers) ----
        float tm0 = -1e30f, tm1 = -1e30f;
#pragma unroll
        for (int j = 0; j < 8; j++) {
            tm0 = fmaxf(tm0, fmaxf(c[j][0], c[j][1]));
            tm1 = fmaxf(tm1, fmaxf(c[j][2], c[j][3]));
        }
        tm0 = fmaxf(tm0, __shfl_xor_sync(0xffffffffu, tm0, 1));
        tm0 = fmaxf(tm0, __shfl_xor_sync(0xffffffffu, tm0, 2));
        tm1 = fmaxf(tm1, __shfl_xor_sync(0xffffffffu, tm1, 1));
        tm1 = fmaxf(tm1, __shfl_xor_sync(0xffffffffu, tm1, 2));

        const float Mn0 = fmaxf(M0, tm0);
        const float Mn1 = fmaxf(M1, tm1);
        const float sc0 = __expf(M0 - Mn0);
        const float sc1 = __expf(M1 - Mn1);
        M0 = Mn0; M1 = Mn1;

        unsigned pA[8], pB[8];
        float s0 = 0.f, s1 = 0.f;
#pragma unroll
        for (int j = 0; j < 8; j++) {
            const unsigned w0 = (j < 4) ? m00 : m01;
            const unsigned w1 = (j < 4) ? m10 : m11;
            const int bit = (j & 3) * 8 + 2 * tig;
            float p00 = __expf(c[j][0] - M0) * (float)((w0 >> bit) & 1u);
            float p01 = __expf(c[j][1] - M0) * (float)((w0 >> (bit + 1)) & 1u);
            float p10 = __expf(c[j][2] - M1) * (float)((w1 >> bit) & 1u);
            float p11 = __expf(c[j][3] - M1) * (float)((w1 >> (bit + 1)) & 1u);
            s0 += p00 + p01;
            s1 += p10 + p11;
            pA[j] = packh2(p00, p01);
            pB[j] = packh2(p10, p11);
        }
        s0 += __shfl_xor_sync(0xffffffffu, s0, 1);
        s0 += __shfl_xor_sync(0xffffffffu, s0, 2);
        s1 += __shfl_xor_sync(0xffffffffu, s1, 1);
        s1 += __shfl_xor_sync(0xffffffffu, s1, 2);
        L0 = L0 * sc0 + s0;
        L1 = L1 * sc1 + s1;
#pragma unroll
        for (int j = 0; j < 8; j++) {
            d[j][0] *= sc0; d[j][1] *= sc0;
            d[j][2] *= sc1; d[j][3] *= sc1;
        }

        // ---- O += P @ V ----
#pragma unroll
        for (int m = 0; m < 4; m++) {
            const int kc = m * 16;
            unsigned bf[8][2];
#pragma unroll
            for (int jp = 0; jp < 4; jp++)
                ldsm4t(bf[2*jp][0], bf[2*jp+1][0], bf[2*jp][1], bf[2*jp+1][1],
                       vsB[s] + (unsigned)(vtOff + kc * KVS + jp * 16) * 2u);
#pragma unroll
            for (int j = 0; j < 8; j++)
                mma16(d[j][0], d[j][1], d[j][2], d[j][3],
                      pA[2*m], pB[2*m], pA[2*m+1], pB[2*m+1],
                      bf[j][0], bf[j][1]);
        }

        __syncthreads();
        if (kt + 2 < 16) {
            issue(kt + 2, s);
            cp_wait<1>();
        } else {
            cp_wait<0>();
        }
        __syncthreads();
    }

    const float i0 = 1.0f / L0;
    const float i1 = 1.0f / L1;
    __half* O0 = CTX + baseo + (size_t)(q0 + warp * 16 + gid)     * DMODEL;
    __half* O1 = CTX + baseo + (size_t)(q0 + warp * 16 + gid + 8) * DMODEL;
#pragma unroll
    for (int j = 0; j < 8; j++) {
        const int col = j * 8 + 2 * tig;
        *(__half2*)(O0 + col) = __floats2half2_rn(d[j][0] * i0, d[j][1] * i0);
        *(__half2*)(O1 + col) = __floats2half2_rn(d[j][2] * i1, d[j][3] * i1);
    }
}

// ---------------------------------------------------------------------------
// Fused residual add + LayerNorm — single barrier, redundant final reduce
// ---------------------------------------------------------------------------
template <int WH>
__global__ void __launch_bounds__(256) add_ln_k(
    const float* __restrict__ A, const float* __restrict__ R,
    const float* __restrict__ g, const float* __restrict__ bta,
    float* __restrict__ O, __half* __restrict__ Oh)
{
    __shared__ float red[16];
    const int row = blockIdx.x;
    const int t   = threadIdx.x;
    const float* a = A + (size_t)row * DMODEL;
    const float* r = R + (size_t)row * DMODEL;

    float v[4];
    float s = 0.f, s2 = 0.f;
#pragma unroll
    for (int i = 0; i < 4; i++) {
        float x = a[t + 256 * i] + r[t + 256 * i];
        v[i] = x;
        s  += x;
        s2 += x * x;
    }
    const int lane = t & 31, wid = t >> 5;
#pragma unroll
    for (int o = 16; o > 0; o >>= 1) {
        s  += __shfl_xor_sync(0xffffffffu, s, o);
        s2 += __shfl_xor_sync(0xffffffffu, s2, o);
    }
    if (lane == 0) { red[wid] = s; red[8 + wid] = s2; }
    __syncthreads();
    float ts = 0.f, ts2 = 0.f;
#pragma unroll
    for (int i = 0; i < 8; i++) { ts += red[i]; ts2 += red[8 + i]; }
    const float mu  = ts * (1.0f / DMODEL);
    const float var = ts2 * (1.0f / DMODEL) - mu * mu;
    const float inv = rsqrtf(var + 1e-5f);

    float* o = O + (size_t)row * DMODEL;
#pragma unroll
    for (int i = 0; i < 4; i++) {
        int c = t + 256 * i;
        float y = (v[i] - mu) * inv * g[c] + bta[c];
        o[c] = y;
        if (WH) Oh[(size_t)row * DMODEL + c] = __float2half(y);
    }
}

// ---------------------------------------------------------------------------
// kernel_launch
// ---------------------------------------------------------------------------
extern "C" void kernel_launch(void* const* d_in, const int* in_sizes, int n_in,
                              void* d_out, int out_size)
{
    const float* X    = (const float*)d_in[0];
    const void*  mask = (const void*)d_in[1];
    const float* Wq   = (const float*)d_in[2];
    const float* Wk   = (const float*)d_in[3];
    const float* Wv   = (const float*)d_in[4];
    const float* Wo   = (const float*)d_in[5];
    const float* ln1g = (const float*)d_in[6];
    const float* ln1b = (const float*)d_in[7];
    const float* W1   = (const float*)d_in[8];
    const float* b1   = (const float*)d_in[9];
    const float* W2   = (const float*)d_in[10];
    const float* b2   = (const float*)d_in[11];
    const float* ln2g = (const float*)d_in[12];
    const float* ln2b = (const float*)d_in[13];
    float* out = (float*)d_out;

    __half *Xh, *QKVh, *CTXh, *X1h, *Hh;
    __half *WqkvTh, *WoTh, *W1Th, *W2Th;
    float *AO, *X1, *F;
    unsigned *MB;
    cudaGetSymbolAddress((void**)&Xh,     g_Xh);
    cudaGetSymbolAddress((void**)&QKVh,   g_QKVh);
    cudaGetSymbolAddress((void**)&CTXh,   g_CTXh);
    cudaGetSymbolAddress((void**)&X1h,    g_X1h);
    cudaGetSymbolAddress((void**)&Hh,     g_Hh);
    cudaGetSymbolAddress((void**)&AO,     g_AO);
    cudaGetSymbolAddress((void**)&X1,     g_X1);
    cudaGetSymbolAddress((void**)&F,      g_F);
    cudaGetSymbolAddress((void**)&MB,     g_MB);
    cudaGetSymbolAddress((void**)&WqkvTh, g_WqkvTh);
    cudaGetSymbolAddress((void**)&WoTh,   g_WoTh);
    cudaGetSymbolAddress((void**)&W1Th,   g_W1Th);
    cudaGetSymbolAddress((void**)&W2Th,   g_W2Th);

    cudaFuncSetAttribute(hgemm_k<0,1>, cudaFuncAttributeMaxDynamicSharedMemorySize, GEMM_SMEM);
    cudaFuncSetAttribute(hgemm_k<0,0>, cudaFuncAttributeMaxDynamicSharedMemorySize, GEMM_SMEM);
    cudaFuncSetAttribute(hgemm_k<2,1>, cudaFuncAttributeMaxDynamicSharedMemorySize, GEMM_SMEM);
    cudaFuncSetAttribute(hgemm_k<1,0>, cudaFuncAttributeMaxDynamicSharedMemorySize, GEMM_SMEM);
    cudaFuncSetAttribute(attn_k,       cudaFuncAttributeMaxDynamicSharedMemorySize, ATTN_SMEM);

    // Prep (attn_k stays at launch index 5 for ncu -s 5)
    f2h_k<<<(NROWS * DMODEL) / 1024, 256>>>(X, Xh, NROWS * DMODEL);        // 0
    maskpack_k<<<MBWORDS / 256, 256>>>(mask, MB);                           // 1
    {
        TPJobs J;                                                           // 2: Wq,Wk,Wv
        J.cnt = 3;
        const float* ins[3] = { Wq, Wk, Wv };
        int c = 0;
        for (int z = 0; z < 3; z++) {
            J.in[z] = ins[z];
            J.out[z] = WqkvTh + (size_t)z * DMODEL * DMODEL;
            J.K[z] = DMODEL; J.N[z] = DMODEL;
            c += (DMODEL / 64) * (DMODEL / 32);
            J.cum[z] = c;
        }
        transp_k<<<c, 256>>>(J);
    }
    {
        TPJobs J;                                                           // 3: Wo,W1,W2
        J.cnt = 3;
        J.in[0] = Wo; J.out[0] = WoTh; J.K[0] = DMODEL; J.N[0] = DMODEL;
        J.cum[0] = (DMODEL / 64) * (DMODEL / 32);
        J.in[1] = W1; J.out[1] = W1Th; J.K[1] = DMODEL; J.N[1] = DFF;
        J.cum[1] = J.cum[0] + (DMODEL / 64) * (DFF / 32);
        J.in[2] = W2; J.out[2] = W2Th; J.K[2] = DFF; J.N[2] = DMODEL;
        J.cum[2] = J.cum[1] + (DFF / 64) * (DMODEL / 32);
        transp_k<<<J.cum[2], 256>>>(J);
    }

    const dim3 gQKV(QKVN / 128, NROWS / 128);   // (24, 64)
    const dim3 gD(DMODEL / 128, NROWS / 128);   // (8, 64)
    const dim3 gF(DFF / 128, NROWS / 128);      // (32, 64)

    // Fused QKV projection                                                 // 4
    hgemm_k<0,1><<<gQKV, 128, GEMM_SMEM>>>(Xh, WqkvTh, nullptr, QKVh, NROWS, QKVN, DMODEL);

    // Flash attention                                                      // 5
    attn_k<<<dim3(SEQ / 128, NHEAD, BATCH), 256, ATTN_SMEM>>>(QKVh, MB, CTXh);

    // Output projection (fp32 out)
    hgemm_k<0,0><<<gD, 128, GEMM_SMEM>>>(CTXh, WoTh, nullptr, AO, NROWS, DMODEL, DMODEL);

    // Residual + LN1 (dual write fp32 + fp16)
    add_ln_k<1><<<NROWS, 256>>>(AO, X, ln1g, ln1b, X1, X1h);

    // FFN
    hgemm_k<2,1><<<gF, 128, GEMM_SMEM>>>(X1h, W1Th, b1, Hh, NROWS, DFF, DMODEL);
    hgemm_k<1,0><<<gD, 128, GEMM_SMEM>>>(Hh, W2Th, b2, F, NROWS, DMODEL, DFF);

    // Residual + LN2 -> output
    add_ln_k<0><<<NROWS, 256>>>(F, X1, ln2g, ln2b, out, nullptr);
}

// round 16
// speedup vs baseline: 1.5279x; 1.0372x over previous
#include <cuda_runtime.h>
#include <cuda_fp16.h>
#include <cstdint>

#define BATCH   8
#define SEQ     1024
#define DMODEL  1024
#define NHEAD   16
#define HDIM    64
#define DFF     4096
#define NROWS   (BATCH * SEQ)           // 8192
#define QKVN    (3 * DMODEL)            // 3072
#define MBWORDS (BATCH * SEQ * SEQ / 32)  // 262144

// ---------------------------------------------------------------------------
// Scratch buffers
// ---------------------------------------------------------------------------
__device__ __half g_Xh   [NROWS * DMODEL];
__device__ __half g_QKVh [NROWS * QKVN];
__device__ __half g_CTXh [NROWS * DMODEL];
__device__ __half g_X1h  [NROWS * DMODEL];
__device__ __half g_Hh   [NROWS * DFF];
__device__ float  g_AO   [NROWS * DMODEL];
__device__ float  g_X1   [NROWS * DMODEL];
__device__ float  g_F    [NROWS * DMODEL];
__device__ unsigned g_MB [MBWORDS];       // bit-packed mask
// transposed fp16 weights [N][K]
__device__ __half g_WqkvTh[QKVN * DMODEL];
__device__ __half g_WoTh  [DMODEL * DMODEL];
__device__ __half g_W1Th  [DFF * DMODEL];
__device__ __half g_W2Th  [DMODEL * DFF];

// ---------------------------------------------------------------------------
// Helpers
// ---------------------------------------------------------------------------
__device__ __forceinline__ unsigned smem_u32(const void* p) {
    return (unsigned)__cvta_generic_to_shared(p);
}
__device__ __forceinline__ void cp16(unsigned s, const void* g) {
    asm volatile("cp.async.cg.shared.global [%0], [%1], 16;" :: "r"(s), "l"(g));
}
__device__ __forceinline__ void cp_commit() {
    asm volatile("cp.async.commit_group;");
}
template <int N>
__device__ __forceinline__ void cp_wait() {
    asm volatile("cp.async.wait_group %0;" :: "n"(N));
}
__device__ __forceinline__ void mma16(
    float& c0, float& c1, float& c2, float& c3,
    unsigned a0, unsigned a1, unsigned a2, unsigned a3,
    unsigned b0, unsigned b1)
{
    asm volatile(
        "mma.sync.aligned.m16n8k16.row.col.f32.f16.f16.f32 "
        "{%0,%1,%2,%3},{%4,%5,%6,%7},{%8,%9},{%0,%1,%2,%3};"
        : "+f"(c0), "+f"(c1), "+f"(c2), "+f"(c3)
        : "r"(a0), "r"(a1), "r"(a2), "r"(a3), "r"(b0), "r"(b1));
}
__device__ __forceinline__ void ldsm4(
    unsigned& r0, unsigned& r1, unsigned& r2, unsigned& r3, unsigned addr)
{
    asm volatile("ldmatrix.sync.aligned.m8n8.x4.shared.b16 {%0,%1,%2,%3}, [%4];"
        : "=r"(r0), "=r"(r1), "=r"(r2), "=r"(r3) : "r"(addr));
}
__device__ __forceinline__ void ldsm4t(
    unsigned& r0, unsigned& r1, unsigned& r2, unsigned& r3, unsigned addr)
{
    asm volatile("ldmatrix.sync.aligned.m8n8.x4.trans.shared.b16 {%0,%1,%2,%3}, [%4];"
        : "=r"(r0), "=r"(r1), "=r"(r2), "=r"(r3) : "r"(addr));
}
__device__ __forceinline__ unsigned packh2(float a, float b) {
    __half2 h = __floats2half2_rn(a, b);
    return *(unsigned*)&h;
}

// ---------------------------------------------------------------------------
// Fused prep kernel: f2h(X) + maskpack + 6 weight transposes in ONE launch.
// Grid layout: [0,8192) f2h | [8192,9216) maskpack | [9216,15360) transposes
// ---------------------------------------------------------------------------
#define PREP_F2H   8192
#define PREP_MASK  1024
#define PREP_TRANS 6144
#define PREP_GRID  (PREP_F2H + PREP_MASK + PREP_TRANS)

struct PrepArgs {
    const float* X; __half* Xh;
    const void* mask; unsigned* MB;
    const float* tin[6];
    __half* tout[6];
    int tK[6], tN[6], tcum[6];
};
__global__ void __launch_bounds__(256) prep_k(PrepArgs P)
{
    __shared__ float tile[64][33];
    const int bid = blockIdx.x;
    const int t = threadIdx.x;

    if (bid < PREP_F2H) {
        // ---- fp32 -> fp16 convert of X ----
        int i = (bid * 256 + t) * 4;
        float4 v = *(const float4*)(P.X + i);
        *(__half2*)(P.Xh + i)     = __floats2half2_rn(v.x, v.y);
        *(__half2*)(P.Xh + i + 2) = __floats2half2_rn(v.z, v.w);
    } else if (bid < PREP_F2H + PREP_MASK) {
        // ---- mask bit-pack (detect elem width from word 0) ----
        const unsigned w0 = *(const unsigned*)P.mask;
        const int mode = (w0 == 0x01010101u) ? 0 : 1;
        const size_t i = (size_t)(bid - PREP_F2H) * 256 + t;
        unsigned w = 0;
        if (mode == 0) {
            const unsigned char* m = (const unsigned char*)P.mask + i * 32;
#pragma unroll
            for (int b = 0; b < 32; b++) w |= (m[b] ? 1u : 0u) << b;
        } else {
            const unsigned* m = (const unsigned*)P.mask + i * 32;
#pragma unroll
            for (int b = 0; b < 32; b++) w |= (m[b] ? 1u : 0u) << b;
        }
        P.MB[i] = w;
    } else {
        // ---- weight transpose: out[n*K+k] = half(in[k*N+n]); 64k x 32n tile
        int lt = bid - (PREP_F2H + PREP_MASK);
        int z = 0;
        while (z < 5 && lt >= P.tcum[z]) z++;
        lt -= (z ? P.tcum[z - 1] : 0);
        const int K = P.tK[z], N = P.tN[z];
        const int ntk = K >> 6;
        const int kb = (lt % ntk) * 64;
        const int nb = (lt / ntk) * 32;
        const float* in = P.tin[z];
        __half* out = P.tout[z];
        const int tx = t & 31, wy = t >> 5;

#pragma unroll
        for (int i = wy; i < 64; i += 8)
            tile[i][tx] = in[(size_t)(kb + i) * N + nb + tx];
        __syncthreads();

#pragma unroll
        for (int p = 0; p < 4; p++) {
            const int n = wy + p * 8;
            __half2 v = __floats2half2_rn(tile[tx * 2][n], tile[tx * 2 + 1][n]);
            *(__half2*)(out + (size_t)(nb + n) * K + kb + tx * 2) = v;
        }
    }
}

// ---------------------------------------------------------------------------
// fp16 GEMM, cp.async 2-stage, LDSM fragments: C = A @ Bt^T (+bias)(+relu)
// ---------------------------------------------------------------------------
#define TS 40
#define HSTAGE (128 * TS)
#define GEMM_SMEM (4 * HSTAGE * 2)    // 40960 B

template <int EPI, int OUTF>
__global__ void __launch_bounds__(128, 2) hgemm_k(
    const __half* __restrict__ A, const __half* __restrict__ Bt,
    const float* __restrict__ bias, void* __restrict__ Cv,
    int M, int N, int K)
{
    extern __shared__ __half hsm[];
    __half* Asm[2] = { hsm,              hsm + HSTAGE     };
    __half* Bsm[2] = { hsm + 2 * HSTAGE, hsm + 3 * HSTAGE };

    const int t    = threadIdx.x;
    const int lane = t & 31, warp = t >> 5;
    const int gid  = lane >> 2, tig = lane & 3;
    const int r8   = lane & 7,  g8  = lane >> 3;
    const int wm   = (warp & 1) * 64;
    const int wn   = (warp >> 1) * 64;
    const int bx   = blockIdx.x, by = blockIdx.y;

    const int lr = t >> 2, lch = (t & 3) * 8;

    const __half* Abase = A  + (size_t)(by * 128 + lr) * K + lch;
    const __half* Bbase = Bt + (size_t)(bx * 128 + lr) * K + lch;

    auto issue = [&](int kt, int s) {
        const __half* Ag = Abase + kt * 32;
        const __half* Bg = Bbase + kt * 32;
        __half* ad = Asm[s];
        __half* bd = Bsm[s];
#pragma unroll
        for (int p = 0; p < 4; p++) {
            cp16(smem_u32(&ad[(lr + p * 32) * TS + lch]), Ag + (size_t)(p * 32) * K);
            cp16(smem_u32(&bd[(lr + p * 32) * TS + lch]), Bg + (size_t)(p * 32) * K);
        }
        cp_commit();
    };

    const int aOff = (wm + r8 + (g8 & 1) * 8) * TS + (g8 >> 1) * 8;
    const int bOff = (wn + r8 + (g8 >> 1) * 8) * TS + (g8 & 1) * 8;
    const unsigned asB[2] = { smem_u32(Asm[0]), smem_u32(Asm[1]) };
    const unsigned bsB[2] = { smem_u32(Bsm[0]), smem_u32(Bsm[1]) };

    float acc[4][8][4];
#pragma unroll
    for (int i = 0; i < 4; i++)
#pragma unroll
        for (int j = 0; j < 8; j++)
#pragma unroll
            for (int r = 0; r < 4; r++) acc[i][j][r] = 0.f;

    const int nkt = K >> 5;
    issue(0, 0);
    issue(1, 1);
    cp_wait<1>();
    __syncthreads();

    for (int kt = 0; kt < nkt; ++kt) {
        const int s = kt & 1;
#pragma unroll
        for (int ks = 0; ks < 2; ++ks) {
            const int kc = ks * 16;
            unsigned af[4][4], bf[8][2];
#pragma unroll
            for (int i = 0; i < 4; i++)
                ldsm4(af[i][0], af[i][1], af[i][2], af[i][3],
                      asB[s] + (unsigned)(aOff + i * 16 * TS + kc) * 2u);
#pragma unroll
            for (int jp = 0; jp < 4; jp++)
                ldsm4(bf[2*jp][0], bf[2*jp][1], bf[2*jp+1][0], bf[2*jp+1][1],
                      bsB[s] + (unsigned)(bOff + jp * 16 * TS + kc) * 2u);
#pragma unroll
            for (int i = 0; i < 4; i++)
#pragma unroll
                for (int j = 0; j < 8; j++)
                    mma16(acc[i][j][0], acc[i][j][1], acc[i][j][2], acc[i][j][3],
                          af[i][0], af[i][1], af[i][2], af[i][3],
                          bf[j][0], bf[j][1]);
        }
        __syncthreads();
        if (kt + 2 < nkt) {
            issue(kt + 2, s);
            cp_wait<1>();
        } else {
            cp_wait<0>();
        }
        __syncthreads();
    }

#pragma unroll
    for (int i = 0; i < 4; i++) {
        const int r0 = by * 128 + wm + i * 16 + gid;
#pragma unroll
        for (int j = 0; j < 8; j++) {
            const int c0 = bx * 128 + wn + j * 8 + 2 * tig;
            float v0 = acc[i][j][0], v1 = acc[i][j][1];
            float v2 = acc[i][j][2], v3 = acc[i][j][3];
            if (EPI >= 1) {
                float b0 = bias[c0], b1 = bias[c0 + 1];
                v0 += b0; v1 += b1; v2 += b0; v3 += b1;
            }
            if (EPI == 2) {
                v0 = fmaxf(v0, 0.f); v1 = fmaxf(v1, 0.f);
                v2 = fmaxf(v2, 0.f); v3 = fmaxf(v3, 0.f);
            }
            if (OUTF == 1) {
                __half* C = (__half*)Cv;
                *(__half2*)(C + (size_t)r0 * N + c0)       = __floats2half2_rn(v0, v1);
                *(__half2*)(C + (size_t)(r0 + 8) * N + c0) = __floats2half2_rn(v2, v3);
            } else {
                float* C = (float*)Cv;
                *(float2*)(C + (size_t)r0 * N + c0)       = make_float2(v0, v1);
                *(float2*)(C + (size_t)(r0 + 8) * N + c0) = make_float2(v2, v3);
            }
        }
    }
}

// ---------------------------------------------------------------------------
// Flash attention: fp16, 2-stage K/V, register P, bit-packed mask.
// Q/K/V in fused QKV buffer [NROWS][3072]: Q@0, K@1024, V@2048.
// ---------------------------------------------------------------------------
#define KVS 72
#define KV_TILEH (64 * KVS)
#define ATTN_SMEM ((4 * KV_TILEH + 128 * KVS) * 2)       // 55296 B

__global__ void __launch_bounds__(256, 1) attn_k(
    const __half* __restrict__ QKV, const unsigned* __restrict__ MB,
    __half* __restrict__ CTX)
{
    extern __shared__ __half smh[];
    __half* ksm[2] = { smh,                smh + KV_TILEH     };
    __half* vsm[2] = { smh + 2 * KV_TILEH, smh + 3 * KV_TILEH };
    __half* ps     = smh + 4 * KV_TILEH;

    const int qb = blockIdx.x, h = blockIdx.y, b = blockIdx.z;
    const int t = threadIdx.x, lane = t & 31, warp = t >> 5;
    const int gid = lane >> 2, tig = lane & 3;
    const int r8 = lane & 7, g8 = lane >> 3;
    const int q0 = qb * 128;
    const size_t baseq = (size_t)b * SEQ * QKVN + (size_t)h * HDIM;
    const size_t baseo = (size_t)b * SEQ * DMODEL + (size_t)h * HDIM;

    const int lr = t >> 3;
    const int lch = (t & 7) * 8;

    auto issue = [&](int kt, int s) {
        const __half* Kg = QKV + baseq + DMODEL     + (size_t)(kt * 64) * QKVN;
        const __half* Vg = QKV + baseq + 2 * DMODEL + (size_t)(kt * 64) * QKVN;
        __half* kd = ksm[s];
        __half* vd = vsm[s];
#pragma unroll
        for (int p = 0; p < 2; p++) {
            int r = p * 32 + lr;
            cp16(smem_u32(&kd[r * KVS + lch]), Kg + (size_t)r * QKVN + lch);
            cp16(smem_u32(&vd[r * KVS + lch]), Vg + (size_t)r * QKVN + lch);
        }
        cp_commit();
    };

    issue(0, 0);
    issue(1, 1);

    __half* pw = ps + warp * 16 * KVS;
    {
        const int row = lane >> 1;
        const int colh = (lane & 1) * 32;
        const uint4* qg4 = (const uint4*)(QKV + baseq + (size_t)(q0 + warp * 16 + row) * QKVN + colh);
        uint4* qp4 = (uint4*)(pw + row * KVS + colh);
#pragma unroll
        for (int i = 0; i < 4; i++) qp4[i] = qg4[i];
    }
    __syncwarp();

    const unsigned pwB = smem_u32(pw);
    const unsigned ksB[2] = { smem_u32(ksm[0]), smem_u32(ksm[1]) };
    const unsigned vsB[2] = { smem_u32(vsm[0]), smem_u32(vsm[1]) };
    const int paOff = (r8 + (g8 & 1) * 8) * KVS + (g8 >> 1) * 8;
    const int sbOff = (r8 + (g8 >> 1) * 8) * KVS + (g8 & 1) * 8;
    const int vtOff = (r8 + (g8 >> 1) * 8) * KVS + (g8 & 1) * 8;

    unsigned aq[4][4];
#pragma unroll
    for (int ks = 0; ks < 4; ks++)
        ldsm4(aq[ks][0], aq[ks][1], aq[ks][2], aq[ks][3],
              pwB + (unsigned)(paOff + ks * 16) * 2u);

    float d[8][4];
#pragma unroll
    for (int j = 0; j < 8; j++)
#pragma unroll
        for (int r = 0; r < 4; r++) d[j][r] = 0.f;
    float M0 = -1e30f, M1 = -1e30f, L0 = 0.f, L1 = 0.f;

    const size_t mw0 = ((size_t)b * SEQ + q0 + warp * 16 + gid) * 32;
    const size_t mw1 = mw0 + 8 * 32;

    cp_wait<1>();
    __syncthreads();

    for (int kt = 0; kt < 16; kt++) {
        const int s = kt & 1;

        const unsigned m00 = MB[mw0 + kt * 2], m01 = MB[mw0 + kt * 2 + 1];
        const unsigned m10 = MB[mw1 + kt * 2], m11 = MB[mw1 + kt * 2 + 1];

        // ---- S = Q K^T ----
        float c[8][4];
#pragma unroll
        for (int j = 0; j < 8; j++)
#pragma unroll
            for (int r = 0; r < 4; r++) c[j][r] = 0.f;
#pragma unroll
        for (int ks = 0; ks < 4; ks++) {
            const int kc = ks * 16;
            unsigned bf[8][2];
#pragma unroll
            for (int jp = 0; jp < 4; jp++)
                ldsm4(bf[2*jp][0], bf[2*jp][1], bf[2*jp+1][0], bf[2*jp+1][1],
                      ksB[s] + (unsigned)(sbOff + jp * 16 * KVS + kc) * 2u);
#pragma unroll
            for (int j = 0; j < 8; j++)
                mma16(c[j][0], c[j][1], c[j][2], c[j][3],
                      aq[ks][0], aq[ks][1], aq[ks][2], aq[ks][3],
                      bf[j][0], bf[j][1]);
        }

        // ---- online softmax (fp32 exp, P packed into registers) ----
        float tm0 = -1e30f, tm1 = -1e30f;
#pragma unroll
        for (int j = 0; j < 8; j++) {
            tm0 = fmaxf(tm0, fmaxf(c[j][0], c[j][1]));
            tm1 = fmaxf(tm1, fmaxf(c[j][2], c[j][3]));
        }
        tm0 = fmaxf(tm0, __shfl_xor_sync(0xffffffffu, tm0, 1));
        tm0 = fmaxf(tm0, __shfl_xor_sync(0xffffffffu, tm0, 2));
        tm1 = fmaxf(tm1, __shfl_xor_sync(0xffffffffu, tm1, 1));
        tm1 = fmaxf(tm1, __shfl_xor_sync(0xffffffffu, tm1, 2));

        const float Mn0 = fmaxf(M0, tm0);
        const float Mn1 = fmaxf(M1, tm1);
        const float sc0 = __expf(M0 - Mn0);
        const float sc1 = __expf(M1 - Mn1);
        M0 = Mn0; M1 = Mn1;

        unsigned pA[8], pB[8];
        float s0 = 0.f, s1 = 0.f;
#pragma unroll
        for (int j = 0; j < 8; j++) {
            const unsigned w0 = (j < 4) ? m00 : m01;
            const unsigned w1 = (j < 4) ? m10 : m11;
            const int bit = (j & 3) * 8 + 2 * tig;
            float p00 = __expf(c[j][0] - M0) * (float)((w0 >> bit) & 1u);
            float p01 = __expf(c[j][1] - M0) * (float)((w0 >> (bit + 1)) & 1u);
            float p10 = __expf(c[j][2] - M1) * (float)((w1 >> bit) & 1u);
            float p11 = __expf(c[j][3] - M1) * (float)((w1 >> (bit + 1)) & 1u);
            s0 += p00 + p01;
            s1 += p10 + p11;
            pA[j] = packh2(p00, p01);
            pB[j] = packh2(p10, p11);
        }
        s0 += __shfl_xor_sync(0xffffffffu, s0, 1);
        s0 += __shfl_xor_sync(0xffffffffu, s0, 2);
        s1 += __shfl_xor_sync(0xffffffffu, s1, 1);
        s1 += __shfl_xor_sync(0xffffffffu, s1, 2);
        L0 = L0 * sc0 + s0;
        L1 = L1 * sc1 + s1;
#pragma unroll
        for (int j = 0; j < 8; j++) {
            d[j][0] *= sc0; d[j][1] *= sc0;
            d[j][2] *= sc1; d[j][3] *= sc1;
        }

        // ---- O += P @ V ----
#pragma unroll
        for (int m = 0; m < 4; m++) {
            const int kc = m * 16;
            unsigned bf[8][2];
#pragma unroll
            for (int jp = 0; jp < 4; jp++)
                ldsm4t(bf[2*jp][0], bf[2*jp+1][0], bf[2*jp][1], bf[2*jp+1][1],
                       vsB[s] + (unsigned)(vtOff + kc * KVS + jp * 16) * 2u);
#pragma unroll
            for (int j = 0; j < 8; j++)
                mma16(d[j][0], d[j][1], d[j][2], d[j][3],
                      pA[2*m], pB[2*m], pA[2*m+1], pB[2*m+1],
                      bf[j][0], bf[j][1]);
        }

        __syncthreads();
        if (kt + 2 < 16) {
            issue(kt + 2, s);
            cp_wait<1>();
        } else {
            cp_wait<0>();
        }
        __syncthreads();
    }

    const float i0 = 1.0f / L0;
    const float i1 = 1.0f / L1;
    __half* O0 = CTX + baseo + (size_t)(q0 + warp * 16 + gid)     * DMODEL;
    __half* O1 = CTX + baseo + (size_t)(q0 + warp * 16 + gid + 8) * DMODEL;
#pragma unroll
    for (int j = 0; j < 8; j++) {
        const int col = j * 8 + 2 * tig;
        *(__half2*)(O0 + col) = __floats2half2_rn(d[j][0] * i0, d[j][1] * i0);
        *(__half2*)(O1 + col) = __floats2half2_rn(d[j][2] * i1, d[j][3] * i1);
    }
}

// ---------------------------------------------------------------------------
// Fused residual add + LayerNorm — single barrier, redundant final reduce
// ---------------------------------------------------------------------------
template <int WH>
__global__ void __launch_bounds__(256) add_ln_k(
    const float* __restrict__ A, const float* __restrict__ R,
    const float* __restrict__ g, const float* __restrict__ bta,
    float* __restrict__ O, __half* __restrict__ Oh)
{
    __shared__ float red[16];
    const int row = blockIdx.x;
    const int t   = threadIdx.x;
    const float* a = A + (size_t)row * DMODEL;
    const float* r = R + (size_t)row * DMODEL;

    float v[4];
    float s = 0.f, s2 = 0.f;
#pragma unroll
    for (int i = 0; i < 4; i++) {
        float x = a[t + 256 * i] + r[t + 256 * i];
        v[i] = x;
        s  += x;
        s2 += x * x;
    }
    const int lane = t & 31, wid = t >> 5;
#pragma unroll
    for (int o = 16; o > 0; o >>= 1) {
        s  += __shfl_xor_sync(0xffffffffu, s, o);
        s2 += __shfl_xor_sync(0xffffffffu, s2, o);
    }
    if (lane == 0) { red[wid] = s; red[8 + wid] = s2; }
    __syncthreads();
    float ts = 0.f, ts2 = 0.f;
#pragma unroll
    for (int i = 0; i < 8; i++) { ts += red[i]; ts2 += red[8 + i]; }
    const float mu  = ts * (1.0f / DMODEL);
    const float var = ts2 * (1.0f / DMODEL) - mu * mu;
    const float inv = rsqrtf(var + 1e-5f);

    float* o = O + (size_t)row * DMODEL;
#pragma unroll
    for (int i = 0; i < 4; i++) {
        int c = t + 256 * i;
        float y = (v[i] - mu) * inv * g[c] + bta[c];
        o[c] = y;
        if (WH) Oh[(size_t)row * DMODEL + c] = __float2half(y);
    }
}

// ---------------------------------------------------------------------------
// kernel_launch
// ---------------------------------------------------------------------------
extern "C" void kernel_launch(void* const* d_in, const int* in_sizes, int n_in,
                              void* d_out, int out_size)
{
    const float* X    = (const float*)d_in[0];
    const void*  mask = (const void*)d_in[1];
    const float* Wq   = (const float*)d_in[2];
    const float* Wk   = (const float*)d_in[3];
    const float* Wv   = (const float*)d_in[4];
    const float* Wo   = (const float*)d_in[5];
    const float* ln1g = (const float*)d_in[6];
    const float* ln1b = (const float*)d_in[7];
    const float* W1   = (const float*)d_in[8];
    const float* b1   = (const float*)d_in[9];
    const float* W2   = (const float*)d_in[10];
    const float* b2   = (const float*)d_in[11];
    const float* ln2g = (const float*)d_in[12];
    const float* ln2b = (const float*)d_in[13];
    float* out = (float*)d_out;

    __half *Xh, *QKVh, *CTXh, *X1h, *Hh;
    __half *WqkvTh, *WoTh, *W1Th, *W2Th;
    float *AO, *X1, *F;
    unsigned *MB;
    cudaGetSymbolAddress((void**)&Xh,     g_Xh);
    cudaGetSymbolAddress((void**)&QKVh,   g_QKVh);
    cudaGetSymbolAddress((void**)&CTXh,   g_CTXh);
    cudaGetSymbolAddress((void**)&X1h,    g_X1h);
    cudaGetSymbolAddress((void**)&Hh,     g_Hh);
    cudaGetSymbolAddress((void**)&AO,     g_AO);
    cudaGetSymbolAddress((void**)&X1,     g_X1);
    cudaGetSymbolAddress((void**)&F,      g_F);
    cudaGetSymbolAddress((void**)&MB,     g_MB);
    cudaGetSymbolAddress((void**)&WqkvTh, g_WqkvTh);
    cudaGetSymbolAddress((void**)&WoTh,   g_WoTh);
    cudaGetSymbolAddress((void**)&W1Th,   g_W1Th);
    cudaGetSymbolAddress((void**)&W2Th,   g_W2Th);

    cudaFuncSetAttribute(hgemm_k<0,1>, cudaFuncAttributeMaxDynamicSharedMemorySize, GEMM_SMEM);
    cudaFuncSetAttribute(hgemm_k<0,0>, cudaFuncAttributeMaxDynamicSharedMemorySize, GEMM_SMEM);
    cudaFuncSetAttribute(hgemm_k<2,1>, cudaFuncAttributeMaxDynamicSharedMemorySize, GEMM_SMEM);
    cudaFuncSetAttribute(hgemm_k<1,0>, cudaFuncAttributeMaxDynamicSharedMemorySize, GEMM_SMEM);
    cudaFuncSetAttribute(attn_k,       cudaFuncAttributeMaxDynamicSharedMemorySize, ATTN_SMEM);

    // Fused prep: f2h + maskpack + all 6 weight transposes          // launch 0
    {
        PrepArgs P;
        P.X = X; P.Xh = Xh; P.mask = mask; P.MB = MB;
        const float* ins[6]  = { Wq, Wk, Wv, Wo, W1, W2 };
        __half* outs[6] = { WqkvTh, WqkvTh + DMODEL * DMODEL,
                            WqkvTh + 2 * DMODEL * DMODEL, WoTh, W1Th, W2Th };
        int Ks[6] = { DMODEL, DMODEL, DMODEL, DMODEL, DMODEL, DFF };
        int Ns[6] = { DMODEL, DMODEL, DMODEL, DMODEL, DFF, DMODEL };
        int c = 0;
        for (int z = 0; z < 6; z++) {
            P.tin[z] = ins[z]; P.tout[z] = outs[z];
            P.tK[z] = Ks[z]; P.tN[z] = Ns[z];
            c += (Ks[z] / 64) * (Ns[z] / 32);
            P.tcum[z] = c;
        }
        prep_k<<<PREP_GRID, 256>>>(P);
    }

    const dim3 gQKV(QKVN / 128, NROWS / 128);   // (24, 64)
    const dim3 gD(DMODEL / 128, NROWS / 128);   // (8, 64)
    const dim3 gF(DFF / 128, NROWS / 128);      // (32, 64)

    // Fused QKV projection                                           // 1
    hgemm_k<0,1><<<gQKV, 128, GEMM_SMEM>>>(Xh, WqkvTh, nullptr, QKVh, NROWS, QKVN, DMODEL);

    // Flash attention                                                // 2
    attn_k<<<dim3(SEQ / 128, NHEAD, BATCH), 256, ATTN_SMEM>>>(QKVh, MB, CTXh);

    // Output projection (fp32 out)                                   // 3
    hgemm_k<0,0><<<gD, 128, GEMM_SMEM>>>(CTXh, WoTh, nullptr, AO, NROWS, DMODEL, DMODEL);

    // Residual + LN1 (dual write fp32 + fp16)                        // 4
    add_ln_k<1><<<NROWS, 256>>>(AO, X, ln1g, ln1b, X1, X1h);

    // FFN                                                            // 5, 6
    hgemm_k<2,1><<<gF, 128, GEMM_SMEM>>>(X1h, W1Th, b1, Hh, NROWS, DFF, DMODEL);
    hgemm_k<1,0><<<gD, 128, GEMM_SMEM>>>(Hh, W2Th, b2, F, NROWS, DMODEL, DFF);

    // Residual + LN2 -> output                                       // 7
    add_ln_k<0><<<NROWS, 256>>>(F, X1, ln2g, ln2b, out, nullptr);
}